// round 6
// baseline (speedup 1.0000x reference)
#include <cuda_runtime.h>
#include <cuda_fp16.h>
#include <math.h>
#include <stdint.h>

// Problem dims
#define B_   256
#define S_   200
#define T_   100
#define F_   10
#define E_   128
#define H_   256
#define G4   1024   // 4*H
#define P1_  512
#define P2_  128

// persistent LSTM config
#define LCTA 64
#define LTHR 256
#define LGRP 32     // arrivals per group barrier (32 n'-slices)

// ---------------- scratch (device globals; no runtime alloc allowed) ----------------
__device__ __half g_eh  [S_*B_*E_];           // e fp16, [s][b][k]
__device__ __half g_Gxh [(size_t)T_*B_*G4];   // x-part+bias fp16, HIST ONLY, [s][b][n']
__device__ __half g_WihPh[G4*E_];             // permuted fp16 [n'][k]
__device__ float  g_WhhP[G4*H_];              // permuted fp32 [n'][k]
__device__ float  g_biasP[G4];
__device__ __half g_W1h[P1_*H_];              // [n][k] fp16
__device__ __half g_W2h[P2_*P1_];             // [n][k] fp16
__device__ __half g_hF[2][B_*H_];             // hidden fp16 [b][u], ping-pong
__device__ float  g_c[B_*H_];                 // final cN [b][u]
__device__ float  g_r[B_*G4];                 // hN @ WhhP^T [b][n']
__device__ __half g_HoutH[T_*B_*H_];          // fp16
__device__ __half g_Z1h[(size_t)T_*B_*P1_];   // fp16
__device__ float  g_Z2[T_*B_*P2_];

// per-group barrier, each on its own 128B line; gen monotonic (replay-safe via snapshot)
struct __align__(256) BarT { int cnt; int pad0[31]; int gen; int pad1[31]; };
__device__ BarT g_bar[4];

__device__ __forceinline__ float sigmf(float x) { return 1.0f / (1.0f + expf(-x)); }

__device__ __forceinline__ int ldacq(const int* p)
{
    int v;
    asm volatile("ld.acquire.gpu.global.b32 %0, [%1];" : "=r"(v) : "l"(p) : "memory");
    return v;
}
__device__ __forceinline__ void strel(int* p, int v)
{
    asm volatile("st.release.gpu.global.b32 [%0], %1;" :: "l"(p), "r"(v) : "memory");
}
__device__ __forceinline__ int atomadd(int* p, int v)
{
    int o;
    asm volatile("atom.acq_rel.gpu.global.add.s32 %0, [%1], %2;"
                 : "=r"(o) : "l"(p), "r"(v) : "memory");
    return o;
}

__device__ __forceinline__ void mma_f16(float* d, const uint32_t* a, const uint32_t* b)
{
    asm volatile(
        "mma.sync.aligned.m16n8k16.row.col.f32.f16.f16.f32 "
        "{%0,%1,%2,%3}, {%4,%5,%6,%7}, {%8,%9}, {%0,%1,%2,%3};\n"
        : "+f"(d[0]), "+f"(d[1]), "+f"(d[2]), "+f"(d[3])
        : "r"(a[0]), "r"(a[1]), "r"(a[2]), "r"(a[3]), "r"(b[0]), "r"(b[1]));
}

__device__ __forceinline__ void ldmx4(uint32_t* r, uint32_t addr)
{
    asm volatile(
        "ldmatrix.sync.aligned.m8n8.x4.shared.b16 {%0,%1,%2,%3}, [%4];\n"
        : "=r"(r[0]), "=r"(r[1]), "=r"(r[2]), "=r"(r[3]) : "r"(addr));
}

__device__ __forceinline__ uint32_t packh2(float lo, float hi)
{
    __half2 h = __floats2half2_rn(lo, hi);
    return *reinterpret_cast<uint32_t*>(&h);
}

// swizzled offset for [128 rows][32 halfs] tiles packed 2 rows per 128B, 16B units
__device__ __forceinline__ int swz16(int r, int u)
{
    return (r >> 1) * 128 + (((((r & 1) << 2) | u) ^ ((r >> 1) & 7)) << 4);
}

// ---------------- small prep kernels ----------------
__global__ void permute_weights(const float* __restrict__ Wih, const float* __restrict__ Whh,
                                const float* __restrict__ bih, const float* __restrict__ bhh)
{
    int np  = blockIdx.x;                 // n' 0..1023
    int src = (np & 3) * H_ + (np >> 2);  // gate*256 + unit
    int t   = threadIdx.x;
    if (t < E_) g_WihPh[np * E_ + t] = __float2half_rn(Wih[src * E_ + t]);
    g_WhhP[np * H_ + t] = Whh[src * H_ + t];
    if (t == 0) g_biasP[np] = bih[src] + bhh[src];
}

__global__ void prep_w1(const float* __restrict__ W1)   // (H,P1) -> [P1][H] fp16
{
    int n = blockIdx.x, k = threadIdx.x;
    g_W1h[n * H_ + k] = __float2half_rn(W1[k * P1_ + n]);
}

__global__ void prep_w2(const float* __restrict__ W2)   // (P1,P2) -> [P2][P1] fp16
{
    int n = blockIdx.x, k = threadIdx.x;
    g_W2h[n * P1_ + k] = __float2half_rn(W2[k * P2_ + n]);
}

__global__ void zero_h0()
{
    int i = blockIdx.x * 256 + threadIdx.x;
    if (i < (B_ * H_) / 2) ((uint32_t*)g_hF[0])[i] = 0;
}

__global__ void embed_mean(const int* __restrict__ x, const float* __restrict__ emb)
{
    int row = blockIdx.x;            // b*S_ + s
    int b = row / S_, s = row % S_;
    const int* xi = x + row * F_;
    int k = threadIdx.x;
    float sum = 0.0f;
#pragma unroll
    for (int f = 0; f < F_; f++) sum += emb[(size_t)xi[f] * E_ + k];
    g_eh[((size_t)s * B_ + b) * E_ + k] = __float2half_rn(sum * (1.0f / (float)F_));
}

// ---------------- fp16 tensor-core GEMM: C = act(A @ B^T + bias) ----------------
template<int RELU, int OUTH>
__global__ void __launch_bounds__(256) gemm_f16(const __half* __restrict__ A,
                                                const __half* __restrict__ Bh,
                                                const float* __restrict__ bias,
                                                void* __restrict__ Cv,
                                                int M, int N, int K)
{
    __shared__ __align__(16) __half As[128 * 32];
    __shared__ __align__(16) __half Bs[128 * 32];

    const int tid  = threadIdx.x;
    const int lane = tid & 31;
    const int warp = tid >> 5;
    const int g    = lane >> 2;
    const int q    = lane & 3;
    const int wm0  = (warp >> 2) << 6;
    const int wn0  = (warp & 3) << 5;
    const int m0   = blockIdx.y << 7;
    const int n0   = blockIdx.x << 7;

    const uint32_t As32 = (uint32_t)__cvta_generic_to_shared(As);
    const uint32_t Bs32 = (uint32_t)__cvta_generic_to_shared(Bs);

    const int lr = tid >> 2;
    const int lu = tid & 3;

    const __half* Ag0 = A  + (size_t)(m0 + lr) * K + lu * 8;
    const __half* Ag1 = Ag0 + (size_t)64 * K;
    const __half* Bg0 = Bh + (size_t)(n0 + lr) * K + lu * 8;
    const __half* Bg1 = Bg0 + (size_t)64 * K;

    float acc[4][4][4];
#pragma unroll
    for (int mi = 0; mi < 4; mi++)
#pragma unroll
        for (int ni = 0; ni < 4; ni++)
#pragma unroll
            for (int r = 0; r < 4; r++) acc[mi][ni][r] = 0.0f;

    uint4 pa0 = *(const uint4*)Ag0;
    uint4 pa1 = *(const uint4*)Ag1;
    uint4 pb0 = *(const uint4*)Bg0;
    uint4 pb1 = *(const uint4*)Bg1;

    const int nchunk = K >> 5;
    for (int ch = 0; ch < nchunk; ch++) {
        *(uint4*)((char*)As + swz16(lr,      lu)) = pa0;
        *(uint4*)((char*)As + swz16(lr + 64, lu)) = pa1;
        *(uint4*)((char*)Bs + swz16(lr,      lu)) = pb0;
        *(uint4*)((char*)Bs + swz16(lr + 64, lu)) = pb1;
        __syncthreads();

        if (ch + 1 < nchunk) {
            int ko = (ch + 1) << 5;
            pa0 = *(const uint4*)(Ag0 + ko);
            pa1 = *(const uint4*)(Ag1 + ko);
            pb0 = *(const uint4*)(Bg0 + ko);
            pb1 = *(const uint4*)(Bg1 + ko);
        }

#pragma unroll
        for (int ks = 0; ks < 2; ks++) {
            const int fu = ks * 2 + (lane >> 4);
            const int fr = lane & 15;
            uint32_t af[4][4], bf[4][2];
#pragma unroll
            for (int mt = 0; mt < 4; mt++)
                ldmx4(af[mt], As32 + swz16(wm0 + mt * 16 + fr, fu));
#pragma unroll
            for (int np = 0; np < 2; np++) {
                uint32_t t[4];
                ldmx4(t, Bs32 + swz16(wn0 + np * 16 + fr, fu));
                bf[2 * np][0]     = t[0];
                bf[2 * np + 1][0] = t[1];
                bf[2 * np][1]     = t[2];
                bf[2 * np + 1][1] = t[3];
            }
#pragma unroll
            for (int mt = 0; mt < 4; mt++)
#pragma unroll
                for (int nt = 0; nt < 4; nt++)
                    mma_f16(acc[mt][nt], af[mt], bf[nt]);
        }
        __syncthreads();
    }

#pragma unroll
    for (int nt = 0; nt < 4; nt++) {
        int cn = n0 + wn0 + nt * 8 + 2 * q;
        float bb0 = bias[cn], bb1 = bias[cn + 1];
#pragma unroll
        for (int mt = 0; mt < 4; mt++) {
            int r0 = m0 + wm0 + mt * 16 + g;
            float v0 = acc[mt][nt][0] + bb0;
            float v1 = acc[mt][nt][1] + bb1;
            float v2 = acc[mt][nt][2] + bb0;
            float v3 = acc[mt][nt][3] + bb1;
            if (RELU) {
                v0 = fmaxf(v0, 0.f); v1 = fmaxf(v1, 0.f);
                v2 = fmaxf(v2, 0.f); v3 = fmaxf(v3, 0.f);
            }
            if (OUTH) {
                __half* Ch = (__half*)Cv;
                *(__half2*)&Ch[(size_t)r0 * N + cn]       = __floats2half2_rn(v0, v1);
                *(__half2*)&Ch[(size_t)(r0 + 8) * N + cn] = __floats2half2_rn(v2, v3);
            } else {
                float* Cf = (float*)Cv;
                *(float2*)&Cf[(size_t)r0 * N + cn]       = make_float2(v0, v1);
                *(float2*)&Cf[(size_t)(r0 + 8) * N + cn] = make_float2(v2, v3);
            }
        }
    }
}

// ---------------- fused tgt kernel: gates(e_tgt @ WihP^T + bias + r[b]) -> Hout fp16 ----
// Same GEMM core (M=T_*B_, N=G4, K=E_); epilogue applies the LSTM gate math against
// cN and writes Hout directly. r (1MB) and cN (256KB) are L2-resident.
__global__ void __launch_bounds__(256) tgt_fused()
{
    __shared__ __align__(16) __half As[128 * 32];
    __shared__ __align__(16) __half Bs[128 * 32];

    const int tid  = threadIdx.x;
    const int lane = tid & 31;
    const int warp = tid >> 5;
    const int g    = lane >> 2;
    const int q    = lane & 3;
    const int wm0  = (warp >> 2) << 6;
    const int wn0  = (warp & 3) << 5;
    const int m0   = blockIdx.y << 7;
    const int n0   = blockIdx.x << 7;

    const uint32_t As32 = (uint32_t)__cvta_generic_to_shared(As);
    const uint32_t Bs32 = (uint32_t)__cvta_generic_to_shared(Bs);

    const int lr = tid >> 2;
    const int lu = tid & 3;

    const __half* A = g_eh + (size_t)T_ * B_ * E_;   // tgt rows
    const __half* Ag0 = A + (size_t)(m0 + lr) * E_ + lu * 8;
    const __half* Ag1 = Ag0 + (size_t)64 * E_;
    const __half* Bg0 = g_WihPh + (size_t)(n0 + lr) * E_ + lu * 8;
    const __half* Bg1 = Bg0 + (size_t)64 * E_;

    float acc[4][4][4];
#pragma unroll
    for (int mi = 0; mi < 4; mi++)
#pragma unroll
        for (int ni = 0; ni < 4; ni++)
#pragma unroll
            for (int r = 0; r < 4; r++) acc[mi][ni][r] = 0.0f;

    uint4 pa0 = *(const uint4*)Ag0;
    uint4 pa1 = *(const uint4*)Ag1;
    uint4 pb0 = *(const uint4*)Bg0;
    uint4 pb1 = *(const uint4*)Bg1;

    const int nchunk = E_ >> 5;   // 4
    for (int ch = 0; ch < nchunk; ch++) {
        *(uint4*)((char*)As + swz16(lr,      lu)) = pa0;
        *(uint4*)((char*)As + swz16(lr + 64, lu)) = pa1;
        *(uint4*)((char*)Bs + swz16(lr,      lu)) = pb0;
        *(uint4*)((char*)Bs + swz16(lr + 64, lu)) = pb1;
        __syncthreads();

        if (ch + 1 < nchunk) {
            int ko = (ch + 1) << 5;
            pa0 = *(const uint4*)(Ag0 + ko);
            pa1 = *(const uint4*)(Ag1 + ko);
            pb0 = *(const uint4*)(Bg0 + ko);
            pb1 = *(const uint4*)(Bg1 + ko);
        }

#pragma unroll
        for (int ks = 0; ks < 2; ks++) {
            const int fu = ks * 2 + (lane >> 4);
            const int fr = lane & 15;
            uint32_t af[4][4], bf[4][2];
#pragma unroll
            for (int mt = 0; mt < 4; mt++)
                ldmx4(af[mt], As32 + swz16(wm0 + mt * 16 + fr, fu));
#pragma unroll
            for (int np = 0; np < 2; np++) {
                uint32_t t[4];
                ldmx4(t, Bs32 + swz16(wn0 + np * 16 + fr, fu));
                bf[2 * np][0]     = t[0];
                bf[2 * np + 1][0] = t[1];
                bf[2 * np][1]     = t[2];
                bf[2 * np + 1][1] = t[3];
            }
#pragma unroll
            for (int mt = 0; mt < 4; mt++)
#pragma unroll
                for (int nt = 0; nt < 4; nt++)
                    mma_f16(acc[mt][nt], af[mt], bf[nt]);
        }
        __syncthreads();
    }

    // gate epilogue
    const int hi = q & 1;
#pragma unroll
    for (int nt = 0; nt < 4; nt++) {
        const int cn = n0 + wn0 + nt * 8 + 2 * q;
        const float bb0 = g_biasP[cn], bb1 = g_biasP[cn + 1];
        const int u = ((n0 + wn0 + nt * 8) >> 2) + (q >> 1);
#pragma unroll
        for (int mt = 0; mt < 4; mt++) {
            const int m_lo = m0 + wm0 + mt * 16 + g;
            const int m_hi = m_lo + 8;
            float2 rlo = *(const float2*)&g_r[(size_t)(m_lo & 255) * G4 + cn];
            float2 rhi = *(const float2*)&g_r[(size_t)(m_hi & 255) * G4 + cn];
            float p0 = acc[mt][nt][0] + bb0 + rlo.x;
            float p1 = acc[mt][nt][1] + bb1 + rlo.y;
            float p2 = acc[mt][nt][2] + bb0 + rhi.x;
            float p3 = acc[mt][nt][3] + bb1 + rhi.y;
            float r0 = __shfl_xor_sync(0xffffffffu, p0, 1);
            float r1 = __shfl_xor_sync(0xffffffffu, p1, 1);
            float r2 = __shfl_xor_sync(0xffffffffu, p2, 1);
            float r3 = __shfl_xor_sync(0xffffffffu, p3, 1);
            float gi = hi ? r2 : p0;
            float gf = hi ? r3 : p1;
            float gg = hi ? p2 : r0;
            float go = hi ? p3 : r1;
            const int m_sel = hi ? m_hi : m_lo;
            const int b_sel = m_sel & 255;
            float cprev = g_c[(size_t)b_sel * H_ + u];
            float c = sigmf(gf) * cprev + sigmf(gi) * tanhf(gg);
            float h = sigmf(go) * tanhf(c);
            g_HoutH[(size_t)m_sel * H_ + u] = __float2half_rn(h);
        }
    }
}

// ---------------- persistent fp16 LSTM, 2-group interleaved ----------------
// 64 CTAs x 256 thr.  cta: pair = cta>>5 (groups {2p, 2p+1}), slice = cta&31 (32 n').
// Each CTA alternates group A / group B per step; the barrier WAIT for a group is
// separated from its ARRIVE by a full phase of the other group's compute -> the
// store->fence->arrive->release->poll->reload chain is overlapped, not serialized.
// W frags shared across both groups (W depends only on n').  c in registers.
__global__ void __launch_bounds__(LTHR, 1) lstm_persist()
{
    __shared__ __align__(16) unsigned char Asm[64 * 512];   // h tile 64b x 256k fp16, swizzled
    __shared__ __align__(16) __half hstg[64 * 8];           // h staging (1KB)

    const int tid  = threadIdx.x;
    const int cta  = blockIdx.x;
    const int lane = tid & 31;
    const int warp = tid >> 5;
    const int g    = lane >> 2;
    const int q    = lane & 3;
    const int wm   = warp & 1;        // batch half (32b)
    const int wn   = warp >> 1;       // n' octet (8 n')
    const int pair = cta >> 5;
    const int slice= cta & 31;
    const int np0  = slice << 5;      // 32 n' per CTA
    const int u0   = slice << 3;      // 8 units per CTA
    const int b0s[2]  = { (pair * 2) << 6, (pair * 2 + 1) << 6 };
    const int grps[2] = { pair * 2, pair * 2 + 1 };

    uint32_t smem_u32 = (uint32_t)__cvta_generic_to_shared(Asm);

    // W fragments (once; shared by both groups)
    uint32_t br[16][2];
    {
        const int np = np0 + wn * 8 + g;
        const float* wp = g_WhhP + (size_t)np * H_;
#pragma unroll
        for (int kc = 0; kc < 16; kc++) {
            float2 lo = *(const float2*)&wp[kc * 16 + 2 * q];
            float2 hi = *(const float2*)&wp[kc * 16 + 2 * q + 8];
            br[kc][0] = packh2(lo.x, lo.y);
            br[kc][1] = packh2(hi.x, hi.y);
        }
    }

    uint32_t abase[2]; int axor[2];
#pragma unroll
    for (int mt = 0; mt < 2; mt++) {
        int ar = wm * 32 + mt * 16 + (lane & 15);
        abase[mt] = smem_u32 + ar * 512;
        axor[mt]  = (ar & 7) << 4;
    }
    const int acol0 = (lane >> 4) * 16;

    // gen snapshots (replay-safe; every member snapshots before its first arrival)
    int gbase[2] = {0, 0};
    if (tid == 0) {
        gbase[0] = ldacq(&g_bar[grps[0]].gen);
        gbase[1] = ldacq(&g_bar[grps[1]].gen);
    }

    float cst[2][2] = {{0.f, 0.f}, {0.f, 0.f}};   // [phase][mt]

    for (int s = 0; s <= T_; s++) {
        const int prv = s & 1;
#pragma unroll
        for (int ph = 0; ph < 2; ph++) {
            const int b0 = b0s[ph], grp = grps[ph];

            // wait for this group's previous step (hidden behind other group's phase)
            if (s > 0) {
                if (tid == 0) {
                    const int tgt = gbase[ph] + s;
                    while (ldacq(&g_bar[grp].gen) - tgt < 0) __nanosleep(20);
                }
                __syncthreads();
            }

            // A-fill: h tile global -> swizzled smem
            {
                const __half* hp = g_hF[prv];
#pragma unroll
                for (int it = 0; it < 8; it++) {
                    int id  = tid + it * LTHR;    // 0..2047 16B units
                    int row = id >> 5;
                    int cu  = id & 31;
                    uint4 v = __ldcg((const uint4*)&hp[(size_t)(b0 + row) * H_ + cu * 8]);
                    int off = row * 512 + ((cu * 16) ^ ((row & 7) << 4));
                    *(uint4*)(Asm + off) = v;
                }
            }
            __syncthreads();

            // Gx prefetch (fp16)
            __half2 gxlo[2], gxhi[2];
            if (s < T_) {
#pragma unroll
                for (int mt = 0; mt < 2; mt++) {
                    const int bg = b0 + wm * 32 + mt * 16 + g;
                    const int nc = np0 + wn * 8 + 2 * q;
                    const __half* gp = g_Gxh + ((size_t)s * B_ + bg) * G4 + nc;
                    gxlo[mt] = *(const __half2*)gp;
                    gxhi[mt] = *(const __half2*)(gp + (size_t)8 * G4);
                }
            }

            // mma mainloop
            float acc[2][4] = {{0.f,0.f,0.f,0.f},{0.f,0.f,0.f,0.f}};
#pragma unroll
            for (int kc = 0; kc < 16; kc++) {
                uint32_t a0[4], a1[4];
                ldmx4(a0, abase[0] + ((acol0 + kc * 32) ^ axor[0]));
                ldmx4(a1, abase[1] + ((acol0 + kc * 32) ^ axor[1]));
                mma_f16(acc[0], a0, br[kc]);
                mma_f16(acc[1], a1, br[kc]);
            }

            if (s < T_) {
                const int hi = q & 1;
#pragma unroll
                for (int mt = 0; mt < 2; mt++) {
                    float2 glo = __half22float2(gxlo[mt]);
                    float2 ghi = __half22float2(gxhi[mt]);
                    float p0 = acc[mt][0] + glo.x;
                    float p1 = acc[mt][1] + glo.y;
                    float p2 = acc[mt][2] + ghi.x;
                    float p3 = acc[mt][3] + ghi.y;
                    float r0 = __shfl_xor_sync(0xffffffffu, p0, 1);
                    float r1 = __shfl_xor_sync(0xffffffffu, p1, 1);
                    float r2 = __shfl_xor_sync(0xffffffffu, p2, 1);
                    float r3 = __shfl_xor_sync(0xffffffffu, p3, 1);
                    float gi = hi ? r2 : p0;
                    float gf = hi ? r3 : p1;
                    float gg = hi ? p2 : r0;
                    float go = hi ? p3 : r1;
                    float c  = sigmf(gf) * cst[ph][mt] + sigmf(gi) * tanhf(gg);
                    cst[ph][mt] = c;
                    float h  = sigmf(go) * tanhf(c);
                    const int bl = wm * 32 + mt * 16 + g + (hi ? 8 : 0);
                    const int ul = wn * 2 + (q >> 1);
                    hstg[bl * 8 + ul] = __float2half_rn(h);
                }
                __syncthreads();

                __half* hnxt = g_hF[prv ^ 1];
                if (tid < 64) {
                    *(uint4*)&hnxt[(size_t)(b0 + tid) * H_ + u0] = *(uint4*)&hstg[tid * 8];
                    __threadfence();
                }
                __syncthreads();

                // arrive only (wait happens next step, after other group's phase)
                if (tid == 0) {
                    int old = atomadd(&g_bar[grp].cnt, 1);
                    if (old == LGRP - 1) {
                        g_bar[grp].cnt = 0;
                        strel(&g_bar[grp].gen, gbase[ph] + s + 1);
                    }
                }
            } else {
                // s == T_: export r = hN @ W^T and cN
                const int hi = q & 1;
#pragma unroll
                for (int mt = 0; mt < 2; mt++) {
                    const int bg = b0 + wm * 32 + mt * 16 + g;
                    const int nc = np0 + wn * 8 + 2 * q;
                    *(float2*)&g_r[(size_t)bg * G4 + nc] =
                        make_float2(acc[mt][0], acc[mt][1]);
                    *(float2*)&g_r[(size_t)(bg + 8) * G4 + nc] =
                        make_float2(acc[mt][2], acc[mt][3]);
                    const int b = bg + (hi ? 8 : 0);
                    const int u = u0 + wn * 2 + (q >> 1);
                    g_c[(size_t)b * H_ + u] = cst[ph][mt];
                }
            }
        }
    }
}

// ---------------- final: out = sigmoid(Z2 @ W3 + b3), remap (t,b) -> (b,t) ----------------
__global__ void final_dot(const float* __restrict__ W3, const float* __restrict__ b3,
                          float* __restrict__ out)
{
    int row  = blockIdx.x * 8 + (threadIdx.x >> 5);
    int lane = threadIdx.x & 31;
    float4 z = *(const float4*)&g_Z2[row * P2_ + lane * 4];
    float4 w = *(const float4*)&W3[lane * 4];
    float s = z.x * w.x + z.y * w.y + z.z * w.z + z.w * w.w;
#pragma unroll
    for (int o = 16; o > 0; o >>= 1) s += __shfl_xor_sync(0xffffffffu, s, o);
    if (lane == 0) {
        int tt = row >> 8, b = row & 255;
        out[b * T_ + tt] = 1.0f / (1.0f + expf(-(s + b3[0])));
    }
}

// ---------------- launcher ----------------
extern "C" void kernel_launch(void* const* d_in, const int* in_sizes, int n_in,
                              void* d_out, int out_size)
{
    const int*   x    = (const int*)  d_in[0];
    const float* emb  = (const float*)d_in[1];
    const float* Wih  = (const float*)d_in[2];
    const float* Whh  = (const float*)d_in[3];
    const float* bih  = (const float*)d_in[4];
    const float* bhh  = (const float*)d_in[5];
    const float* W1   = (const float*)d_in[6];
    const float* b1   = (const float*)d_in[7];
    const float* W2   = (const float*)d_in[8];
    const float* b2   = (const float*)d_in[9];
    const float* W3   = (const float*)d_in[10];
    const float* b3   = (const float*)d_in[11];
    float* out = (float*)d_out;

    void *peh, *pGxh, *pWihPh, *pbias, *pHoutH, *pZ1h, *pZ2, *pW1h, *pW2h;
    cudaGetSymbolAddress(&peh,    g_eh);
    cudaGetSymbolAddress(&pGxh,   g_Gxh);
    cudaGetSymbolAddress(&pWihPh, g_WihPh);
    cudaGetSymbolAddress(&pbias,  g_biasP);
    cudaGetSymbolAddress(&pHoutH, g_HoutH);
    cudaGetSymbolAddress(&pZ1h,   g_Z1h);
    cudaGetSymbolAddress(&pZ2,    g_Z2);
    cudaGetSymbolAddress(&pW1h,   g_W1h);
    cudaGetSymbolAddress(&pW2h,   g_W2h);

    // prep
    permute_weights<<<G4, 256>>>(Wih, Whh, bih, bhh);
    prep_w1<<<P1_, H_>>>(W1);
    prep_w2<<<P2_, P1_>>>(W2);
    zero_h0<<<(B_ * H_ / 2 + 255) / 256, 256>>>();
    embed_mean<<<B_ * S_, E_>>>(x, emb);

    // x-part for HIST positions only (fp16 out, bias folded)
    gemm_f16<0, 1><<<dim3(G4 / 128, (T_ * B_) / 128), 256>>>(
        (const __half*)peh, (const __half*)pWihPh, (const float*)pbias, pGxh,
        T_ * B_, G4, E_);

    // ALL 100 LSTM steps + r = hN@W, 2-group interleaved persistent kernel
    lstm_persist<<<LCTA, LTHR>>>();

    // fused tgt: GEMM + gates -> Hout fp16
    tgt_fused<<<dim3(G4 / 128, (T_ * B_) / 128), 256>>>();

    // MLP (fp16 tensor cores)
    gemm_f16<1, 1><<<dim3(P1_ / 128, (T_ * B_) / 128), 256>>>(
        (const __half*)pHoutH, (const __half*)pW1h, b1, pZ1h, T_ * B_, P1_, H_);
    gemm_f16<1, 0><<<dim3(P2_ / 128, (T_ * B_) / 128), 256>>>(
        (const __half*)pZ1h, (const __half*)pW2h, b2, pZ2, T_ * B_, P2_, P1_);

    // head + layout remap to (B, T)
    final_dot<<<(T_ * B_) / 8, 256>>>(W3, b3, out);
}

// round 7
// speedup vs baseline: 1.1782x; 1.1782x over previous
#include <cuda_runtime.h>
#include <cuda_fp16.h>
#include <math.h>
#include <stdint.h>

// Problem dims
#define B_   256
#define S_   200
#define T_   100
#define F_   10
#define E_   128
#define H_   256
#define G4   1024   // 4*H
#define P1_  512
#define P2_  128

// ---------------- scratch (device globals; no runtime alloc allowed) ----------------
__device__ __half g_eh  [S_*B_*E_];           // e fp16, [s][b][k]
__device__ __half g_Gxh [(size_t)T_*B_*G4];   // x-part+bias fp16, HIST ONLY, [s][b][n']
__device__ __half g_WihPh[G4*E_];             // permuted fp16 [n'][k]
__device__ float  g_WhhP[G4*H_];              // permuted fp32 [n'][k]
__device__ float  g_biasP[G4];
__device__ __half g_W1h[P1_*H_];              // [n][k] fp16
__device__ __half g_W2h[P2_*P1_];             // [n][k] fp16
__device__ __half g_hF[2][B_*H_];             // hidden fp16 [b][u], ping-pong
__device__ float  g_c[B_*H_];                 // final cN [b][u]
__device__ float  g_r[B_*G4];                 // hN @ WhhP^T [b][n']
__device__ __half g_HoutH[T_*B_*H_];          // fp16
__device__ __half g_Z1h[(size_t)T_*B_*P1_];   // fp16
__device__ float  g_Z2[T_*B_*P2_];

__device__ __forceinline__ float sigmf(float x) { return 1.0f / (1.0f + expf(-x)); }

__device__ __forceinline__ void mma_f16(float* d, const uint32_t* a, const uint32_t* b)
{
    asm volatile(
        "mma.sync.aligned.m16n8k16.row.col.f32.f16.f16.f32 "
        "{%0,%1,%2,%3}, {%4,%5,%6,%7}, {%8,%9}, {%0,%1,%2,%3};\n"
        : "+f"(d[0]), "+f"(d[1]), "+f"(d[2]), "+f"(d[3])
        : "r"(a[0]), "r"(a[1]), "r"(a[2]), "r"(a[3]), "r"(b[0]), "r"(b[1]));
}

__device__ __forceinline__ void ldmx4(uint32_t* r, uint32_t addr)
{
    asm volatile(
        "ldmatrix.sync.aligned.m8n8.x4.shared.b16 {%0,%1,%2,%3}, [%4];\n"
        : "=r"(r[0]), "=r"(r[1]), "=r"(r[2]), "=r"(r[3]) : "r"(addr));
}

__device__ __forceinline__ uint32_t packh2(float lo, float hi)
{
    __half2 h = __floats2half2_rn(lo, hi);
    return *reinterpret_cast<uint32_t*>(&h);
}

// swizzled offset for [rows][32 halfs-per-64B-span] tiles, 16B units
__device__ __forceinline__ int swz16(int r, int u)
{
    return (r >> 1) * 128 + (((((r & 1) << 2) | u) ^ ((r >> 1) & 7)) << 4);
}

// ---------------- small prep kernels ----------------
__global__ void permute_weights(const float* __restrict__ Wih, const float* __restrict__ Whh,
                                const float* __restrict__ bih, const float* __restrict__ bhh)
{
    int np  = blockIdx.x;                 // n' 0..1023
    int src = (np & 3) * H_ + (np >> 2);  // gate*256 + unit
    int t   = threadIdx.x;
    if (t < E_) g_WihPh[np * E_ + t] = __float2half_rn(Wih[src * E_ + t]);
    g_WhhP[np * H_ + t] = Whh[src * H_ + t];
    if (t == 0) g_biasP[np] = bih[src] + bhh[src];
}

__global__ void prep_w1(const float* __restrict__ W1)   // (H,P1) -> [P1][H] fp16
{
    int n = blockIdx.x, k = threadIdx.x;
    g_W1h[n * H_ + k] = __float2half_rn(W1[k * P1_ + n]);
}

__global__ void prep_w2(const float* __restrict__ W2)   // (P1,P2) -> [P2][P1] fp16
{
    int n = blockIdx.x, k = threadIdx.x;
    g_W2h[n * P1_ + k] = __float2half_rn(W2[k * P2_ + n]);
}

__global__ void zero_h0()
{
    int i = blockIdx.x * 256 + threadIdx.x;
    if (i < (B_ * H_) / 2) ((uint32_t*)g_hF[0])[i] = 0;
}

__global__ void embed_mean(const int* __restrict__ x, const float* __restrict__ emb)
{
    int row = blockIdx.x;            // b*S_ + s
    int b = row / S_, s = row % S_;
    const int* xi = x + row * F_;
    int k = threadIdx.x;
    float sum = 0.0f;
#pragma unroll
    for (int f = 0; f < F_; f++) sum += emb[(size_t)xi[f] * E_ + k];
    g_eh[((size_t)s * B_ + b) * E_ + k] = __float2half_rn(sum * (1.0f / (float)F_));
}

// ---------------- fp16 tensor-core GEMM: C = act(A @ B^T + bias) ----------------
template<int RELU, int OUTH>
__global__ void __launch_bounds__(256) gemm_f16(const __half* __restrict__ A,
                                                const __half* __restrict__ Bh,
                                                const float* __restrict__ bias,
                                                void* __restrict__ Cv,
                                                int M, int N, int K)
{
    __shared__ __align__(16) __half As[128 * 32];
    __shared__ __align__(16) __half Bs[128 * 32];

    const int tid  = threadIdx.x;
    const int lane = tid & 31;
    const int warp = tid >> 5;
    const int g    = lane >> 2;
    const int q    = lane & 3;
    const int wm0  = (warp >> 2) << 6;
    const int wn0  = (warp & 3) << 5;
    const int m0   = blockIdx.y << 7;
    const int n0   = blockIdx.x << 7;

    const uint32_t As32 = (uint32_t)__cvta_generic_to_shared(As);
    const uint32_t Bs32 = (uint32_t)__cvta_generic_to_shared(Bs);

    const int lr = tid >> 2;
    const int lu = tid & 3;

    const __half* Ag0 = A  + (size_t)(m0 + lr) * K + lu * 8;
    const __half* Ag1 = Ag0 + (size_t)64 * K;
    const __half* Bg0 = Bh + (size_t)(n0 + lr) * K + lu * 8;
    const __half* Bg1 = Bg0 + (size_t)64 * K;

    float acc[4][4][4];
#pragma unroll
    for (int mi = 0; mi < 4; mi++)
#pragma unroll
        for (int ni = 0; ni < 4; ni++)
#pragma unroll
            for (int r = 0; r < 4; r++) acc[mi][ni][r] = 0.0f;

    uint4 pa0 = *(const uint4*)Ag0;
    uint4 pa1 = *(const uint4*)Ag1;
    uint4 pb0 = *(const uint4*)Bg0;
    uint4 pb1 = *(const uint4*)Bg1;

    const int nchunk = K >> 5;
    for (int ch = 0; ch < nchunk; ch++) {
        *(uint4*)((char*)As + swz16(lr,      lu)) = pa0;
        *(uint4*)((char*)As + swz16(lr + 64, lu)) = pa1;
        *(uint4*)((char*)Bs + swz16(lr,      lu)) = pb0;
        *(uint4*)((char*)Bs + swz16(lr + 64, lu)) = pb1;
        __syncthreads();

        if (ch + 1 < nchunk) {
            int ko = (ch + 1) << 5;
            pa0 = *(const uint4*)(Ag0 + ko);
            pa1 = *(const uint4*)(Ag1 + ko);
            pb0 = *(const uint4*)(Bg0 + ko);
            pb1 = *(const uint4*)(Bg1 + ko);
        }

#pragma unroll
        for (int ks = 0; ks < 2; ks++) {
            const int fu = ks * 2 + (lane >> 4);
            const int fr = lane & 15;
            uint32_t af[4][4], bf[4][2];
#pragma unroll
            for (int mt = 0; mt < 4; mt++)
                ldmx4(af[mt], As32 + swz16(wm0 + mt * 16 + fr, fu));
#pragma unroll
            for (int np = 0; np < 2; np++) {
                uint32_t t[4];
                ldmx4(t, Bs32 + swz16(wn0 + np * 16 + fr, fu));
                bf[2 * np][0]     = t[0];
                bf[2 * np + 1][0] = t[1];
                bf[2 * np][1]     = t[2];
                bf[2 * np + 1][1] = t[3];
            }
#pragma unroll
            for (int mt = 0; mt < 4; mt++)
#pragma unroll
                for (int nt = 0; nt < 4; nt++)
                    mma_f16(acc[mt][nt], af[mt], bf[nt]);
        }
        __syncthreads();
    }

#pragma unroll
    for (int nt = 0; nt < 4; nt++) {
        int cn = n0 + wn0 + nt * 8 + 2 * q;
        float bb0 = bias[cn], bb1 = bias[cn + 1];
#pragma unroll
        for (int mt = 0; mt < 4; mt++) {
            int r0 = m0 + wm0 + mt * 16 + g;
            float v0 = acc[mt][nt][0] + bb0;
            float v1 = acc[mt][nt][1] + bb1;
            float v2 = acc[mt][nt][2] + bb0;
            float v3 = acc[mt][nt][3] + bb1;
            if (RELU) {
                v0 = fmaxf(v0, 0.f); v1 = fmaxf(v1, 0.f);
                v2 = fmaxf(v2, 0.f); v3 = fmaxf(v3, 0.f);
            }
            if (OUTH) {
                __half* Ch = (__half*)Cv;
                *(__half2*)&Ch[(size_t)r0 * N + cn]       = __floats2half2_rn(v0, v1);
                *(__half2*)&Ch[(size_t)(r0 + 8) * N + cn] = __floats2half2_rn(v2, v3);
            } else {
                float* Cf = (float*)Cv;
                *(float2*)&Cf[(size_t)r0 * N + cn]       = make_float2(v0, v1);
                *(float2*)&Cf[(size_t)(r0 + 8) * N + cn] = make_float2(v2, v3);
            }
        }
    }
}

// ---------------- fused tgt kernel: gates(e_tgt @ WihP^T + bias + r[b]) -> Hout fp16 ----
__global__ void __launch_bounds__(256) tgt_fused()
{
    __shared__ __align__(16) __half As[128 * 32];
    __shared__ __align__(16) __half Bs[128 * 32];

    const int tid  = threadIdx.x;
    const int lane = tid & 31;
    const int warp = tid >> 5;
    const int g    = lane >> 2;
    const int q    = lane & 3;
    const int wm0  = (warp >> 2) << 6;
    const int wn0  = (warp & 3) << 5;
    const int m0   = blockIdx.y << 7;
    const int n0   = blockIdx.x << 7;

    const uint32_t As32 = (uint32_t)__cvta_generic_to_shared(As);
    const uint32_t Bs32 = (uint32_t)__cvta_generic_to_shared(Bs);

    const int lr = tid >> 2;
    const int lu = tid & 3;

    const __half* A = g_eh + (size_t)T_ * B_ * E_;   // tgt rows
    const __half* Ag0 = A + (size_t)(m0 + lr) * E_ + lu * 8;
    const __half* Ag1 = Ag0 + (size_t)64 * E_;
    const __half* Bg0 = g_WihPh + (size_t)(n0 + lr) * E_ + lu * 8;
    const __half* Bg1 = Bg0 + (size_t)64 * E_;

    float acc[4][4][4];
#pragma unroll
    for (int mi = 0; mi < 4; mi++)
#pragma unroll
        for (int ni = 0; ni < 4; ni++)
#pragma unroll
            for (int r = 0; r < 4; r++) acc[mi][ni][r] = 0.0f;

    uint4 pa0 = *(const uint4*)Ag0;
    uint4 pa1 = *(const uint4*)Ag1;
    uint4 pb0 = *(const uint4*)Bg0;
    uint4 pb1 = *(const uint4*)Bg1;

    const int nchunk = E_ >> 5;   // 4
    for (int ch = 0; ch < nchunk; ch++) {
        *(uint4*)((char*)As + swz16(lr,      lu)) = pa0;
        *(uint4*)((char*)As + swz16(lr + 64, lu)) = pa1;
        *(uint4*)((char*)Bs + swz16(lr,      lu)) = pb0;
        *(uint4*)((char*)Bs + swz16(lr + 64, lu)) = pb1;
        __syncthreads();

        if (ch + 1 < nchunk) {
            int ko = (ch + 1) << 5;
            pa0 = *(const uint4*)(Ag0 + ko);
            pa1 = *(const uint4*)(Ag1 + ko);
            pb0 = *(const uint4*)(Bg0 + ko);
            pb1 = *(const uint4*)(Bg1 + ko);
        }

#pragma unroll
        for (int ks = 0; ks < 2; ks++) {
            const int fu = ks * 2 + (lane >> 4);
            const int fr = lane & 15;
            uint32_t af[4][4], bf[4][2];
#pragma unroll
            for (int mt = 0; mt < 4; mt++)
                ldmx4(af[mt], As32 + swz16(wm0 + mt * 16 + fr, fu));
#pragma unroll
            for (int np = 0; np < 2; np++) {
                uint32_t t[4];
                ldmx4(t, Bs32 + swz16(wn0 + np * 16 + fr, fu));
                bf[2 * np][0]     = t[0];
                bf[2 * np + 1][0] = t[1];
                bf[2 * np][1]     = t[2];
                bf[2 * np + 1][1] = t[3];
            }
#pragma unroll
            for (int mt = 0; mt < 4; mt++)
#pragma unroll
                for (int nt = 0; nt < 4; nt++)
                    mma_f16(acc[mt][nt], af[mt], bf[nt]);
        }
        __syncthreads();
    }

    // gate epilogue
    const int hi = q & 1;
#pragma unroll
    for (int nt = 0; nt < 4; nt++) {
        const int cn = n0 + wn0 + nt * 8 + 2 * q;
        const float bb0 = g_biasP[cn], bb1 = g_biasP[cn + 1];
        const int u = ((n0 + wn0 + nt * 8) >> 2) + (q >> 1);
#pragma unroll
        for (int mt = 0; mt < 4; mt++) {
            const int m_lo = m0 + wm0 + mt * 16 + g;
            const int m_hi = m_lo + 8;
            float2 rlo = *(const float2*)&g_r[(size_t)(m_lo & 255) * G4 + cn];
            float2 rhi = *(const float2*)&g_r[(size_t)(m_hi & 255) * G4 + cn];
            float p0 = acc[mt][nt][0] + bb0 + rlo.x;
            float p1 = acc[mt][nt][1] + bb1 + rlo.y;
            float p2 = acc[mt][nt][2] + bb0 + rhi.x;
            float p3 = acc[mt][nt][3] + bb1 + rhi.y;
            float r0 = __shfl_xor_sync(0xffffffffu, p0, 1);
            float r1 = __shfl_xor_sync(0xffffffffu, p1, 1);
            float r2 = __shfl_xor_sync(0xffffffffu, p2, 1);
            float r3 = __shfl_xor_sync(0xffffffffu, p3, 1);
            float gi = hi ? r2 : p0;
            float gf = hi ? r3 : p1;
            float gg = hi ? p2 : r0;
            float go = hi ? p3 : r1;
            const int m_sel = hi ? m_hi : m_lo;
            const int b_sel = m_sel & 255;
            float cprev = g_c[(size_t)b_sel * H_ + u];
            float c = sigmf(gf) * cprev + sigmf(gi) * tanhf(gg);
            float h = sigmf(go) * tanhf(c);
            g_HoutH[(size_t)m_sel * H_ + u] = __float2half_rn(h);
        }
    }
}

// ---------------- persistent fp16 LSTM with 8-CTA clusters ----------------
// 32 CTAs x 256 thr, cluster (8,1,1).  Cluster = one batch group (64 rows);
// CTA = n' slice [rank*128, +128) -> produces h units [rank*32, +32).
// Per step: swizzled fill of full h tile (L2), ldmatrix+HMMA (W frags in regs),
// gate epilogue, 4KB coalesced h-slice store, ONE barrier.cluster (release/acquire
// covers the global h stores; also flushes L1D so __ldcg/fill stays coherent).
// No atomics, no global barrier state, nothing to reset across graph replays.
__global__ void __launch_bounds__(256, 1) __cluster_dims__(8, 1, 1) lstm_persist()
{
    __shared__ __align__(16) unsigned char Asm[64 * 512];   // h tile 64b x 256u fp16, swizzled
    __shared__ __align__(16) __half hstg[64 * 32];          // h slice staging (4KB)

    const int tid  = threadIdx.x;
    const int lane = tid & 31;
    const int warp = tid >> 5;
    const int g    = lane >> 2;
    const int q    = lane & 3;
    const int wn   = warp;                 // 8 warps x 16 n'
    const int grp  = blockIdx.x >> 3;      // batch group 0..3
    const int rank = blockIdx.x & 7;       // cluster rank = n' slice
    const int b0   = grp << 6;
    const int np0  = rank << 7;            // 128 n' per CTA
    const int u0   = rank << 5;            // 32 units per CTA

    uint32_t smem_u32 = (uint32_t)__cvta_generic_to_shared(Asm);

    // ---- W fragments into registers (once): warp covers 16 n' (nt=2) ----
    uint32_t br[2][16][2];
#pragma unroll
    for (int nt = 0; nt < 2; nt++) {
        const int np = np0 + wn * 16 + nt * 8 + g;
        const float* wp = g_WhhP + (size_t)np * H_;
#pragma unroll
        for (int kc = 0; kc < 16; kc++) {
            float2 lo = *(const float2*)&wp[kc * 16 + 2 * q];
            float2 hi = *(const float2*)&wp[kc * 16 + 2 * q + 8];
            br[nt][kc][0] = packh2(lo.x, lo.y);
            br[nt][kc][1] = packh2(hi.x, hi.y);
        }
    }

    // ldmatrix addresses: 4 m-tiles cover the 64 batch rows
    uint32_t abase[4]; int axor[4];
#pragma unroll
    for (int mt = 0; mt < 4; mt++) {
        int ar = mt * 16 + (lane & 15);
        abase[mt] = smem_u32 + ar * 512;
        axor[mt]  = (ar & 7) << 4;
    }
    const int acol0 = (lane >> 4) * 16;

    float cst[4][2];
#pragma unroll
    for (int mt = 0; mt < 4; mt++) { cst[mt][0] = 0.f; cst[mt][1] = 0.f; }

    for (int s = 0; s <= T_; s++) {
        const int prv = s & 1;

        // A-fill: full 64b x 256u h tile from global -> swizzled smem
        {
            const __half* hp = g_hF[prv];
#pragma unroll
            for (int it = 0; it < 8; it++) {
                int id  = tid + it * 256;     // 0..2047 16B units
                int row = id >> 5;
                int cu  = id & 31;
                uint4 v = __ldcg((const uint4*)&hp[(size_t)(b0 + row) * H_ + cu * 8]);
                int off = row * 512 + ((cu * 16) ^ ((row & 7) << 4));
                *(uint4*)(Asm + off) = v;
            }
        }

        // Gx prefetch (fp16; overlaps with fill latency)
        __half2 gxv[4][2][2];
        if (s < T_) {
#pragma unroll
            for (int mt = 0; mt < 4; mt++)
#pragma unroll
                for (int nt = 0; nt < 2; nt++) {
                    const int bg = b0 + mt * 16 + g;
                    const int nc = np0 + wn * 16 + nt * 8 + 2 * q;
                    const __half* gp = g_Gxh + ((size_t)s * B_ + bg) * G4 + nc;
                    gxv[mt][nt][0] = *(const __half2*)gp;
                    gxv[mt][nt][1] = *(const __half2*)(gp + (size_t)8 * G4);
                }
        }
        __syncthreads();

        // mma mainloop: 4 m-tiles x 2 n-tiles x 16 k-chunks
        float acc[4][2][4];
#pragma unroll
        for (int mt = 0; mt < 4; mt++)
#pragma unroll
            for (int nt = 0; nt < 2; nt++)
#pragma unroll
                for (int r = 0; r < 4; r++) acc[mt][nt][r] = 0.f;

#pragma unroll
        for (int kc = 0; kc < 16; kc++) {
            uint32_t af[4][4];
#pragma unroll
            for (int mt = 0; mt < 4; mt++)
                ldmx4(af[mt], abase[mt] + ((acol0 + kc * 32) ^ axor[mt]));
#pragma unroll
            for (int mt = 0; mt < 4; mt++) {
                mma_f16(acc[mt][0], af[mt], br[0][kc]);
                mma_f16(acc[mt][1], af[mt], br[1][kc]);
            }
        }

        if (s < T_) {
            // gate epilogue -> smem staging
            const int hi = q & 1;
#pragma unroll
            for (int mt = 0; mt < 4; mt++)
#pragma unroll
                for (int nt = 0; nt < 2; nt++) {
                    float2 glo = __half22float2(gxv[mt][nt][0]);
                    float2 ghi = __half22float2(gxv[mt][nt][1]);
                    float p0 = acc[mt][nt][0] + glo.x;
                    float p1 = acc[mt][nt][1] + glo.y;
                    float p2 = acc[mt][nt][2] + ghi.x;
                    float p3 = acc[mt][nt][3] + ghi.y;
                    float r0 = __shfl_xor_sync(0xffffffffu, p0, 1);
                    float r1 = __shfl_xor_sync(0xffffffffu, p1, 1);
                    float r2 = __shfl_xor_sync(0xffffffffu, p2, 1);
                    float r3 = __shfl_xor_sync(0xffffffffu, p3, 1);
                    float gi = hi ? r2 : p0;
                    float gf = hi ? r3 : p1;
                    float gg = hi ? p2 : r0;
                    float go = hi ? p3 : r1;
                    float c  = sigmf(gf) * cst[mt][nt] + sigmf(gi) * tanhf(gg);
                    cst[mt][nt] = c;
                    float h  = sigmf(go) * tanhf(c);
                    const int bl = mt * 16 + g + (hi ? 8 : 0);
                    const int ul = wn * 4 + nt * 2 + (q >> 1);
                    hstg[bl * 32 + ul] = __float2half_rn(h);
                }
            __syncthreads();

            // coalesced 4KB h-slice store: 256 x uint4 (1 per thread)
            {
                __half* hnxt = g_hF[prv ^ 1];
                int row = tid >> 2, j = tid & 3;
                *(uint4*)&hnxt[(size_t)(b0 + row) * H_ + u0 + j * 8] =
                    *(uint4*)&hstg[row * 32 + j * 8];
            }

            // ONE hw cluster barrier: release h stores, acquire peers' stores,
            // flushes L1D; also makes it safe to refill Asm next iteration.
            asm volatile("barrier.cluster.arrive.aligned;" ::: "memory");
            asm volatile("barrier.cluster.wait.aligned;" ::: "memory");
        } else {
            // s == T_: export r = hN @ W^T and cN
            const int hi = q & 1;
#pragma unroll
            for (int mt = 0; mt < 4; mt++)
#pragma unroll
                for (int nt = 0; nt < 2; nt++) {
                    const int m_lo = b0 + mt * 16 + g;
                    const int nc = np0 + wn * 16 + nt * 8 + 2 * q;
                    *(float2*)&g_r[(size_t)m_lo * G4 + nc] =
                        make_float2(acc[mt][nt][0], acc[mt][nt][1]);
                    *(float2*)&g_r[(size_t)(m_lo + 8) * G4 + nc] =
                        make_float2(acc[mt][nt][2], acc[mt][nt][3]);
                    const int b = m_lo + (hi ? 8 : 0);
                    const int u = u0 + wn * 4 + nt * 2 + (q >> 1);
                    g_c[(size_t)b * H_ + u] = cst[mt][nt];
                }
        }
    }
}

// ---------------- final: out = sigmoid(Z2 @ W3 + b3), remap (t,b) -> (b,t) ----------------
__global__ void final_dot(const float* __restrict__ W3, const float* __restrict__ b3,
                          float* __restrict__ out)
{
    int row  = blockIdx.x * 8 + (threadIdx.x >> 5);
    int lane = threadIdx.x & 31;
    float4 z = *(const float4*)&g_Z2[row * P2_ + lane * 4];
    float4 w = *(const float4*)&W3[lane * 4];
    float s = z.x * w.x + z.y * w.y + z.z * w.z + z.w * w.w;
#pragma unroll
    for (int o = 16; o > 0; o >>= 1) s += __shfl_xor_sync(0xffffffffu, s, o);
    if (lane == 0) {
        int tt = row >> 8, b = row & 255;
        out[b * T_ + tt] = 1.0f / (1.0f + expf(-(s + b3[0])));
    }
}

// ---------------- launcher ----------------
extern "C" void kernel_launch(void* const* d_in, const int* in_sizes, int n_in,
                              void* d_out, int out_size)
{
    const int*   x    = (const int*)  d_in[0];
    const float* emb  = (const float*)d_in[1];
    const float* Wih  = (const float*)d_in[2];
    const float* Whh  = (const float*)d_in[3];
    const float* bih  = (const float*)d_in[4];
    const float* bhh  = (const float*)d_in[5];
    const float* W1   = (const float*)d_in[6];
    const float* b1   = (const float*)d_in[7];
    const float* W2   = (const float*)d_in[8];
    const float* b2   = (const float*)d_in[9];
    const float* W3   = (const float*)d_in[10];
    const float* b3   = (const float*)d_in[11];
    float* out = (float*)d_out;

    void *peh, *pGxh, *pWihPh, *pbias, *pHoutH, *pZ1h, *pZ2, *pW1h, *pW2h;
    cudaGetSymbolAddress(&peh,    g_eh);
    cudaGetSymbolAddress(&pGxh,   g_Gxh);
    cudaGetSymbolAddress(&pWihPh, g_WihPh);
    cudaGetSymbolAddress(&pbias,  g_biasP);
    cudaGetSymbolAddress(&pHoutH, g_HoutH);
    cudaGetSymbolAddress(&pZ1h,   g_Z1h);
    cudaGetSymbolAddress(&pZ2,    g_Z2);
    cudaGetSymbolAddress(&pW1h,   g_W1h);
    cudaGetSymbolAddress(&pW2h,   g_W2h);

    // prep
    permute_weights<<<G4, 256>>>(Wih, Whh, bih, bhh);
    prep_w1<<<P1_, H_>>>(W1);
    prep_w2<<<P2_, P1_>>>(W2);
    zero_h0<<<(B_ * H_ / 2 + 255) / 256, 256>>>();
    embed_mean<<<B_ * S_, E_>>>(x, emb);

    // x-part for HIST positions only (fp16 out, bias folded)
    gemm_f16<0, 1><<<dim3(G4 / 128, (T_ * B_) / 128), 256>>>(
        (const __half*)peh, (const __half*)pWihPh, (const float*)pbias, pGxh,
        T_ * B_, G4, E_);

    // ALL 100 LSTM steps + r = hN@W: clustered persistent kernel (hw barriers)
    lstm_persist<<<32, 256>>>();

    // fused tgt: GEMM + gates -> Hout fp16
    tgt_fused<<<dim3(G4 / 128, (T_ * B_) / 128), 256>>>();

    // MLP (fp16 tensor cores)
    gemm_f16<1, 1><<<dim3(P1_ / 128, (T_ * B_) / 128), 256>>>(
        (const __half*)pHoutH, (const __half*)pW1h, b1, pZ1h, T_ * B_, P1_, H_);
    gemm_f16<1, 0><<<dim3(P2_ / 128, (T_ * B_) / 128), 256>>>(
        (const __half*)pZ1h, (const __half*)pW2h, b2, pZ2, T_ * B_, P2_, P1_);

    // head + layout remap to (B, T)
    final_dot<<<(T_ * B_) / 8, 256>>>(W3, b3, out);
}

// round 8
// speedup vs baseline: 1.7889x; 1.5183x over previous
#include <cuda_runtime.h>
#include <cuda_fp16.h>
#include <math.h>
#include <stdint.h>

// Problem dims
#define B_   256
#define S_   200
#define T_   100
#define F_   10
#define E_   128
#define H_   256
#define G4   1024   // 4*H
#define P1_  512
#define P2_  128

// ---------------- scratch (device globals; no runtime alloc allowed) ----------------
__device__ __half g_eh  [S_*B_*E_];           // e fp16, [s][b][k]
__device__ __half g_Gxh [(size_t)T_*B_*G4];   // x-part+bias fp16, HIST ONLY, [s][b][n']
__device__ __half g_WihPh[G4*E_];             // permuted fp16 [n'][k]
__device__ float  g_WhhP[G4*H_];              // permuted fp32 [n'][k]
__device__ float  g_biasP[G4];
__device__ __half g_W1h[P1_*H_];              // [n][k] fp16
__device__ __half g_W2h[P2_*P1_];             // [n][k] fp16
__device__ __half g_hF[2][B_*H_];             // hidden fp16 [b][u], ping-pong
__device__ float  g_c[B_*H_];                 // final cN [b][u]
__device__ float  g_r[B_*G4];                 // hN @ WhhP^T [b][n']
__device__ __half g_HoutH[T_*B_*H_];          // fp16
__device__ __half g_Z1h[(size_t)T_*B_*P1_];   // fp16
__device__ float  g_Z2[T_*B_*P2_];

// fast gate math: __expf (MUFU EX2) + fast div; rel err ~1e-6, negligible vs budget
__device__ __forceinline__ float fsig(float x)
{
    return __fdividef(1.0f, 1.0f + __expf(-x));
}
__device__ __forceinline__ float ftanh(float x)
{
    return __fdividef(2.0f, 1.0f + __expf(-2.0f * x)) - 1.0f;
}

__device__ __forceinline__ void mma_f16(float* d, const uint32_t* a, const uint32_t* b)
{
    asm volatile(
        "mma.sync.aligned.m16n8k16.row.col.f32.f16.f16.f32 "
        "{%0,%1,%2,%3}, {%4,%5,%6,%7}, {%8,%9}, {%0,%1,%2,%3};\n"
        : "+f"(d[0]), "+f"(d[1]), "+f"(d[2]), "+f"(d[3])
        : "r"(a[0]), "r"(a[1]), "r"(a[2]), "r"(a[3]), "r"(b[0]), "r"(b[1]));
}

__device__ __forceinline__ void ldmx4(uint32_t* r, uint32_t addr)
{
    asm volatile(
        "ldmatrix.sync.aligned.m8n8.x4.shared.b16 {%0,%1,%2,%3}, [%4];\n"
        : "=r"(r[0]), "=r"(r[1]), "=r"(r[2]), "=r"(r[3]) : "r"(addr));
}

__device__ __forceinline__ uint32_t packh2(float lo, float hi)
{
    __half2 h = __floats2half2_rn(lo, hi);
    return *reinterpret_cast<uint32_t*>(&h);
}

// swizzled offset for [rows][32 halfs] tiles, 16B units
__device__ __forceinline__ int swz16(int r, int u)
{
    return (r >> 1) * 128 + (((((r & 1) << 2) | u) ^ ((r >> 1) & 7)) << 4);
}

// ---------------- fused prep: permute + W1/W2 transpose + zero h0 (ONE launch) -----
__global__ void prep_all(const float* __restrict__ Wih, const float* __restrict__ Whh,
                         const float* __restrict__ bih, const float* __restrict__ bhh,
                         const float* __restrict__ W1,  const float* __restrict__ W2)
{
    int blk = blockIdx.x;
    int t   = threadIdx.x;
    if (blk < G4) {                               // permute LSTM weights
        int np  = blk;
        int src = (np & 3) * H_ + (np >> 2);
        if (t < E_) g_WihPh[np * E_ + t] = __float2half_rn(Wih[src * E_ + t]);
        g_WhhP[np * H_ + t] = Whh[src * H_ + t];
        if (t == 0) g_biasP[np] = bih[src] + bhh[src];
    } else if (blk < G4 + P1_) {                  // W1 (H,P1) -> [P1][H] fp16
        int n = blk - G4;
        g_W1h[n * H_ + t] = __float2half_rn(W1[t * P1_ + n]);
    } else if (blk < G4 + P1_ + P2_) {            // W2 (P1,P2) -> [P2][P1] fp16
        int n = blk - G4 - P1_;
        g_W2h[n * P1_ + t]       = __float2half_rn(W2[t * P2_ + n]);
        g_W2h[n * P1_ + t + 256] = __float2half_rn(W2[(t + 256) * P2_ + n]);
    } else {                                      // zero h0 (64 blocks x 256 = 16384 u32)
        int i = (blk - G4 - P1_ - P2_) * 256 + t;
        ((uint32_t*)g_hF[0])[i] = 0;
    }
}

__global__ void embed_mean(const int* __restrict__ x, const float* __restrict__ emb)
{
    int row = blockIdx.x;            // b*S_ + s
    int b = row / S_, s = row % S_;
    const int* xi = x + row * F_;
    int k = threadIdx.x;
    float sum = 0.0f;
#pragma unroll
    for (int f = 0; f < F_; f++) sum += emb[(size_t)xi[f] * E_ + k];
    g_eh[((size_t)s * B_ + b) * E_ + k] = __float2half_rn(sum * (1.0f / (float)F_));
}

// ---------------- fp16 tensor-core GEMM: C = act(A @ B^T + bias) ----------------
template<int RELU, int OUTH>
__global__ void __launch_bounds__(256) gemm_f16(const __half* __restrict__ A,
                                                const __half* __restrict__ Bh,
                                                const float* __restrict__ bias,
                                                void* __restrict__ Cv,
                                                int M, int N, int K)
{
    __shared__ __align__(16) __half As[128 * 32];
    __shared__ __align__(16) __half Bs[128 * 32];

    const int tid  = threadIdx.x;
    const int lane = tid & 31;
    const int warp = tid >> 5;
    const int g    = lane >> 2;
    const int q    = lane & 3;
    const int wm0  = (warp >> 2) << 6;
    const int wn0  = (warp & 3) << 5;
    const int m0   = blockIdx.y << 7;
    const int n0   = blockIdx.x << 7;

    const uint32_t As32 = (uint32_t)__cvta_generic_to_shared(As);
    const uint32_t Bs32 = (uint32_t)__cvta_generic_to_shared(Bs);

    const int lr = tid >> 2;
    const int lu = tid & 3;

    const __half* Ag0 = A  + (size_t)(m0 + lr) * K + lu * 8;
    const __half* Ag1 = Ag0 + (size_t)64 * K;
    const __half* Bg0 = Bh + (size_t)(n0 + lr) * K + lu * 8;
    const __half* Bg1 = Bg0 + (size_t)64 * K;

    float acc[4][4][4];
#pragma unroll
    for (int mi = 0; mi < 4; mi++)
#pragma unroll
        for (int ni = 0; ni < 4; ni++)
#pragma unroll
            for (int r = 0; r < 4; r++) acc[mi][ni][r] = 0.0f;

    uint4 pa0 = *(const uint4*)Ag0;
    uint4 pa1 = *(const uint4*)Ag1;
    uint4 pb0 = *(const uint4*)Bg0;
    uint4 pb1 = *(const uint4*)Bg1;

    const int nchunk = K >> 5;
    for (int ch = 0; ch < nchunk; ch++) {
        *(uint4*)((char*)As + swz16(lr,      lu)) = pa0;
        *(uint4*)((char*)As + swz16(lr + 64, lu)) = pa1;
        *(uint4*)((char*)Bs + swz16(lr,      lu)) = pb0;
        *(uint4*)((char*)Bs + swz16(lr + 64, lu)) = pb1;
        __syncthreads();

        if (ch + 1 < nchunk) {
            int ko = (ch + 1) << 5;
            pa0 = *(const uint4*)(Ag0 + ko);
            pa1 = *(const uint4*)(Ag1 + ko);
            pb0 = *(const uint4*)(Bg0 + ko);
            pb1 = *(const uint4*)(Bg1 + ko);
        }

#pragma unroll
        for (int ks = 0; ks < 2; ks++) {
            const int fu = ks * 2 + (lane >> 4);
            const int fr = lane & 15;
            uint32_t af[4][4], bf[4][2];
#pragma unroll
            for (int mt = 0; mt < 4; mt++)
                ldmx4(af[mt], As32 + swz16(wm0 + mt * 16 + fr, fu));
#pragma unroll
            for (int np = 0; np < 2; np++) {
                uint32_t t[4];
                ldmx4(t, Bs32 + swz16(wn0 + np * 16 + fr, fu));
                bf[2 * np][0]     = t[0];
                bf[2 * np + 1][0] = t[1];
                bf[2 * np][1]     = t[2];
                bf[2 * np + 1][1] = t[3];
            }
#pragma unroll
            for (int mt = 0; mt < 4; mt++)
#pragma unroll
                for (int nt = 0; nt < 4; nt++)
                    mma_f16(acc[mt][nt], af[mt], bf[nt]);
        }
        __syncthreads();
    }

#pragma unroll
    for (int nt = 0; nt < 4; nt++) {
        int cn = n0 + wn0 + nt * 8 + 2 * q;
        float bb0 = bias[cn], bb1 = bias[cn + 1];
#pragma unroll
        for (int mt = 0; mt < 4; mt++) {
            int r0 = m0 + wm0 + mt * 16 + g;
            float v0 = acc[mt][nt][0] + bb0;
            float v1 = acc[mt][nt][1] + bb1;
            float v2 = acc[mt][nt][2] + bb0;
            float v3 = acc[mt][nt][3] + bb1;
            if (RELU) {
                v0 = fmaxf(v0, 0.f); v1 = fmaxf(v1, 0.f);
                v2 = fmaxf(v2, 0.f); v3 = fmaxf(v3, 0.f);
            }
            if (OUTH) {
                __half* Ch = (__half*)Cv;
                *(__half2*)&Ch[(size_t)r0 * N + cn]       = __floats2half2_rn(v0, v1);
                *(__half2*)&Ch[(size_t)(r0 + 8) * N + cn] = __floats2half2_rn(v2, v3);
            } else {
                float* Cf = (float*)Cv;
                *(float2*)&Cf[(size_t)r0 * N + cn]       = make_float2(v0, v1);
                *(float2*)&Cf[(size_t)(r0 + 8) * N + cn] = make_float2(v2, v3);
            }
        }
    }
}

// ---------------- persistent fp16 LSTM: 8 clusters x 8 CTAs ----------------
// 64 CTAs x 256 thr, cluster (8,1,1).  Cluster = batch group of 32 rows;
// CTA = n' slice [rank*128, +128) -> h units [rank*32, +32).
// Per step: 16KB swizzled fill (L2), ldmatrix+HMMA (W frags in regs), FAST gate
// epilogue, 2KB coalesced h-slice store, ONE barrier.cluster.
__global__ void __launch_bounds__(256, 1) __cluster_dims__(8, 1, 1) lstm_persist()
{
    __shared__ __align__(16) unsigned char Asm[32 * 512];   // h tile 32b x 256u fp16, swizzled
    __shared__ __align__(16) __half hstg[32 * 32];          // h slice staging (2KB)

    const int tid  = threadIdx.x;
    const int lane = tid & 31;
    const int warp = tid >> 5;
    const int g    = lane >> 2;
    const int q    = lane & 3;
    const int wn   = warp;                 // 8 warps x 16 n'
    const int grp  = blockIdx.x >> 3;      // batch group 0..7 (32 rows each)
    const int rank = blockIdx.x & 7;       // n' slice
    const int b0   = grp << 5;
    const int np0  = rank << 7;            // 128 n' per CTA
    const int u0   = rank << 5;            // 32 units per CTA

    uint32_t smem_u32 = (uint32_t)__cvta_generic_to_shared(Asm);

    // W fragments into registers (once): warp covers 16 n' (nt=2)
    uint32_t br[2][16][2];
#pragma unroll
    for (int nt = 0; nt < 2; nt++) {
        const int np = np0 + wn * 16 + nt * 8 + g;
        const float* wp = g_WhhP + (size_t)np * H_;
#pragma unroll
        for (int kc = 0; kc < 16; kc++) {
            float2 lo = *(const float2*)&wp[kc * 16 + 2 * q];
            float2 hi = *(const float2*)&wp[kc * 16 + 2 * q + 8];
            br[nt][kc][0] = packh2(lo.x, lo.y);
            br[nt][kc][1] = packh2(hi.x, hi.y);
        }
    }

    // ldmatrix addresses: 2 m-tiles cover the 32 batch rows
    uint32_t abase[2]; int axor[2];
#pragma unroll
    for (int mt = 0; mt < 2; mt++) {
        int ar = mt * 16 + (lane & 15);
        abase[mt] = smem_u32 + ar * 512;
        axor[mt]  = (ar & 7) << 4;
    }
    const int acol0 = (lane >> 4) * 16;

    float cst[2][2] = {{0.f, 0.f}, {0.f, 0.f}};

    for (int s = 0; s <= T_; s++) {
        const int prv = s & 1;

        // A-fill: 32b x 256u h tile, global -> swizzled smem (4 uint4/thread)
        {
            const __half* hp = g_hF[prv];
#pragma unroll
            for (int it = 0; it < 4; it++) {
                int id  = tid + it * 256;     // 0..1023 16B units
                int row = id >> 5;
                int cu  = id & 31;
                uint4 v = __ldcg((const uint4*)&hp[(size_t)(b0 + row) * H_ + cu * 8]);
                int off = row * 512 + ((cu * 16) ^ ((row & 7) << 4));
                *(uint4*)(Asm + off) = v;
            }
        }

        // Gx prefetch (fp16; overlaps with fill latency)
        __half2 gxv[2][2][2];
        if (s < T_) {
#pragma unroll
            for (int mt = 0; mt < 2; mt++)
#pragma unroll
                for (int nt = 0; nt < 2; nt++) {
                    const int bg = b0 + mt * 16 + g;
                    const int nc = np0 + wn * 16 + nt * 8 + 2 * q;
                    const __half* gp = g_Gxh + ((size_t)s * B_ + bg) * G4 + nc;
                    gxv[mt][nt][0] = *(const __half2*)gp;
                    gxv[mt][nt][1] = *(const __half2*)(gp + (size_t)8 * G4);
                }
        }
        __syncthreads();

        // mma mainloop: 2 m-tiles x 2 n-tiles x 16 k-chunks
        float acc[2][2][4];
#pragma unroll
        for (int mt = 0; mt < 2; mt++)
#pragma unroll
            for (int nt = 0; nt < 2; nt++)
#pragma unroll
                for (int r = 0; r < 4; r++) acc[mt][nt][r] = 0.f;

#pragma unroll
        for (int kc = 0; kc < 16; kc++) {
            uint32_t af[2][4];
#pragma unroll
            for (int mt = 0; mt < 2; mt++)
                ldmx4(af[mt], abase[mt] + ((acol0 + kc * 32) ^ axor[mt]));
#pragma unroll
            for (int mt = 0; mt < 2; mt++) {
                mma_f16(acc[mt][0], af[mt], br[0][kc]);
                mma_f16(acc[mt][1], af[mt], br[1][kc]);
            }
        }

        if (s < T_) {
            // FAST gate epilogue -> smem staging
            const int hi = q & 1;
#pragma unroll
            for (int mt = 0; mt < 2; mt++)
#pragma unroll
                for (int nt = 0; nt < 2; nt++) {
                    float2 glo = __half22float2(gxv[mt][nt][0]);
                    float2 ghi = __half22float2(gxv[mt][nt][1]);
                    float p0 = acc[mt][nt][0] + glo.x;
                    float p1 = acc[mt][nt][1] + glo.y;
                    float p2 = acc[mt][nt][2] + ghi.x;
                    float p3 = acc[mt][nt][3] + ghi.y;
                    float r0 = __shfl_xor_sync(0xffffffffu, p0, 1);
                    float r1 = __shfl_xor_sync(0xffffffffu, p1, 1);
                    float r2 = __shfl_xor_sync(0xffffffffu, p2, 1);
                    float r3 = __shfl_xor_sync(0xffffffffu, p3, 1);
                    float gi = hi ? r2 : p0;
                    float gf = hi ? r3 : p1;
                    float gg = hi ? p2 : r0;
                    float go = hi ? p3 : r1;
                    float c  = fsig(gf) * cst[mt][nt] + fsig(gi) * ftanh(gg);
                    cst[mt][nt] = c;
                    float h  = fsig(go) * ftanh(c);
                    const int bl = mt * 16 + g + (hi ? 8 : 0);
                    const int ul = wn * 4 + nt * 2 + (q >> 1);
                    hstg[bl * 32 + ul] = __float2half_rn(h);
                }
            __syncthreads();

            // coalesced 2KB h-slice store: 128 x uint4
            if (tid < 128) {
                __half* hnxt = g_hF[prv ^ 1];
                int row = tid >> 2, j = tid & 3;
                *(uint4*)&hnxt[(size_t)(b0 + row) * H_ + u0 + j * 8] =
                    *(uint4*)&hstg[row * 32 + j * 8];
            }

            // ONE hw cluster barrier (release stores / acquire peers / L1D flush)
            asm volatile("barrier.cluster.arrive.aligned;" ::: "memory");
            asm volatile("barrier.cluster.wait.aligned;" ::: "memory");
        } else {
            // s == T_: export r = hN @ W^T and cN
            const int hi = q & 1;
#pragma unroll
            for (int mt = 0; mt < 2; mt++)
#pragma unroll
                for (int nt = 0; nt < 2; nt++) {
                    const int m_lo = b0 + mt * 16 + g;
                    const int nc = np0 + wn * 16 + nt * 8 + 2 * q;
                    *(float2*)&g_r[(size_t)m_lo * G4 + nc] =
                        make_float2(acc[mt][nt][0], acc[mt][nt][1]);
                    *(float2*)&g_r[(size_t)(m_lo + 8) * G4 + nc] =
                        make_float2(acc[mt][nt][2], acc[mt][nt][3]);
                    const int b = m_lo + (hi ? 8 : 0);
                    const int u = u0 + wn * 4 + nt * 2 + (q >> 1);
                    g_c[(size_t)b * H_ + u] = cst[mt][nt];
                }
        }
    }
}

// ---------------- fused tgt kernel: gates(e_tgt @ WihP^T + bias + r[b]) -> Hout fp16 ----
__global__ void __launch_bounds__(256) tgt_fused()
{
    __shared__ __align__(16) __half As[128 * 32];
    __shared__ __align__(16) __half Bs[128 * 32];

    const int tid  = threadIdx.x;
    const int lane = tid & 31;
    const int warp = tid >> 5;
    const int g    = lane >> 2;
    const int q    = lane & 3;
    const int wm0  = (warp >> 2) << 6;
    const int wn0  = (warp & 3) << 5;
    const int m0   = blockIdx.y << 7;
    const int n0   = blockIdx.x << 7;

    const uint32_t As32 = (uint32_t)__cvta_generic_to_shared(As);
    const uint32_t Bs32 = (uint32_t)__cvta_generic_to_shared(Bs);

    const int lr = tid >> 2;
    const int lu = tid & 3;

    const __half* A = g_eh + (size_t)T_ * B_ * E_;   // tgt rows
    const __half* Ag0 = A + (size_t)(m0 + lr) * E_ + lu * 8;
    const __half* Ag1 = Ag0 + (size_t)64 * E_;
    const __half* Bg0 = g_WihPh + (size_t)(n0 + lr) * E_ + lu * 8;
    const __half* Bg1 = Bg0 + (size_t)64 * E_;

    float acc[4][4][4];
#pragma unroll
    for (int mi = 0; mi < 4; mi++)
#pragma unroll
        for (int ni = 0; ni < 4; ni++)
#pragma unroll
            for (int r = 0; r < 4; r++) acc[mi][ni][r] = 0.0f;

    uint4 pa0 = *(const uint4*)Ag0;
    uint4 pa1 = *(const uint4*)Ag1;
    uint4 pb0 = *(const uint4*)Bg0;
    uint4 pb1 = *(const uint4*)Bg1;

    const int nchunk = E_ >> 5;   // 4
    for (int ch = 0; ch < nchunk; ch++) {
        *(uint4*)((char*)As + swz16(lr,      lu)) = pa0;
        *(uint4*)((char*)As + swz16(lr + 64, lu)) = pa1;
        *(uint4*)((char*)Bs + swz16(lr,      lu)) = pb0;
        *(uint4*)((char*)Bs + swz16(lr + 64, lu)) = pb1;
        __syncthreads();

        if (ch + 1 < nchunk) {
            int ko = (ch + 1) << 5;
            pa0 = *(const uint4*)(Ag0 + ko);
            pa1 = *(const uint4*)(Ag1 + ko);
            pb0 = *(const uint4*)(Bg0 + ko);
            pb1 = *(const uint4*)(Bg1 + ko);
        }

#pragma unroll
        for (int ks = 0; ks < 2; ks++) {
            const int fu = ks * 2 + (lane >> 4);
            const int fr = lane & 15;
            uint32_t af[4][4], bf[4][2];
#pragma unroll
            for (int mt = 0; mt < 4; mt++)
                ldmx4(af[mt], As32 + swz16(wm0 + mt * 16 + fr, fu));
#pragma unroll
            for (int np = 0; np < 2; np++) {
                uint32_t t[4];
                ldmx4(t, Bs32 + swz16(wn0 + np * 16 + fr, fu));
                bf[2 * np][0]     = t[0];
                bf[2 * np + 1][0] = t[1];
                bf[2 * np][1]     = t[2];
                bf[2 * np + 1][1] = t[3];
            }
#pragma unroll
            for (int mt = 0; mt < 4; mt++)
#pragma unroll
                for (int nt = 0; nt < 4; nt++)
                    mma_f16(acc[mt][nt], af[mt], bf[nt]);
        }
        __syncthreads();
    }

    // fast gate epilogue
    const int hi = q & 1;
#pragma unroll
    for (int nt = 0; nt < 4; nt++) {
        const int cn = n0 + wn0 + nt * 8 + 2 * q;
        const float bb0 = g_biasP[cn], bb1 = g_biasP[cn + 1];
        const int u = ((n0 + wn0 + nt * 8) >> 2) + (q >> 1);
#pragma unroll
        for (int mt = 0; mt < 4; mt++) {
            const int m_lo = m0 + wm0 + mt * 16 + g;
            const int m_hi = m_lo + 8;
            float2 rlo = *(const float2*)&g_r[(size_t)(m_lo & 255) * G4 + cn];
            float2 rhi = *(const float2*)&g_r[(size_t)(m_hi & 255) * G4 + cn];
            float p0 = acc[mt][nt][0] + bb0 + rlo.x;
            float p1 = acc[mt][nt][1] + bb1 + rlo.y;
            float p2 = acc[mt][nt][2] + bb0 + rhi.x;
            float p3 = acc[mt][nt][3] + bb1 + rhi.y;
            float r0 = __shfl_xor_sync(0xffffffffu, p0, 1);
            float r1 = __shfl_xor_sync(0xffffffffu, p1, 1);
            float r2 = __shfl_xor_sync(0xffffffffu, p2, 1);
            float r3 = __shfl_xor_sync(0xffffffffu, p3, 1);
            float gi = hi ? r2 : p0;
            float gf = hi ? r3 : p1;
            float gg = hi ? p2 : r0;
            float go = hi ? p3 : r1;
            const int m_sel = hi ? m_hi : m_lo;
            const int b_sel = m_sel & 255;
            float cprev = g_c[(size_t)b_sel * H_ + u];
            float c = fsig(gf) * cprev + fsig(gi) * ftanh(gg);
            float h = fsig(go) * ftanh(c);
            g_HoutH[(size_t)m_sel * H_ + u] = __float2half_rn(h);
        }
    }
}

// ---------------- final: out = sigmoid(Z2 @ W3 + b3), remap (t,b) -> (b,t) ----------------
__global__ void final_dot(const float* __restrict__ W3, const float* __restrict__ b3,
                          float* __restrict__ out)
{
    int row  = blockIdx.x * 8 + (threadIdx.x >> 5);
    int lane = threadIdx.x & 31;
    float4 z = *(const float4*)&g_Z2[row * P2_ + lane * 4];
    float4 w = *(const float4*)&W3[lane * 4];
    float s = z.x * w.x + z.y * w.y + z.z * w.z + z.w * w.w;
#pragma unroll
    for (int o = 16; o > 0; o >>= 1) s += __shfl_xor_sync(0xffffffffu, s, o);
    if (lane == 0) {
        int tt = row >> 8, b = row & 255;
        out[b * T_ + tt] = fsig(s + b3[0]);
    }
}

// ---------------- launcher ----------------
extern "C" void kernel_launch(void* const* d_in, const int* in_sizes, int n_in,
                              void* d_out, int out_size)
{
    const int*   x    = (const int*)  d_in[0];
    const float* emb  = (const float*)d_in[1];
    const float* Wih  = (const float*)d_in[2];
    const float* Whh  = (const float*)d_in[3];
    const float* bih  = (const float*)d_in[4];
    const float* bhh  = (const float*)d_in[5];
    const float* W1   = (const float*)d_in[6];
    const float* b1   = (const float*)d_in[7];
    const float* W2   = (const float*)d_in[8];
    const float* b2   = (const float*)d_in[9];
    const float* W3   = (const float*)d_in[10];
    const float* b3   = (const float*)d_in[11];
    float* out = (float*)d_out;

    void *peh, *pGxh, *pWihPh, *pbias, *pHoutH, *pZ1h, *pZ2, *pW1h, *pW2h;
    cudaGetSymbolAddress(&peh,    g_eh);
    cudaGetSymbolAddress(&pGxh,   g_Gxh);
    cudaGetSymbolAddress(&pWihPh, g_WihPh);
    cudaGetSymbolAddress(&pbias,  g_biasP);
    cudaGetSymbolAddress(&pHoutH, g_HoutH);
    cudaGetSymbolAddress(&pZ1h,   g_Z1h);
    cudaGetSymbolAddress(&pZ2,    g_Z2);
    cudaGetSymbolAddress(&pW1h,   g_W1h);
    cudaGetSymbolAddress(&pW2h,   g_W2h);

    // 1: fused prep (permute + W1/W2 transpose + zero h0)
    prep_all<<<G4 + P1_ + P2_ + 64, 256>>>(Wih, Whh, bih, bhh, W1, W2);

    // 2: embedding mean
    embed_mean<<<B_ * S_, E_>>>(x, emb);

    // 3: x-part for HIST positions (fp16 out, bias folded)
    gemm_f16<0, 1><<<dim3(G4 / 128, (T_ * B_) / 128), 256>>>(
        (const __half*)peh, (const __half*)pWihPh, (const float*)pbias, pGxh,
        T_ * B_, G4, E_);

    // 4 (PROFILED): all 100 LSTM steps + r = hN@W, clustered persistent kernel
    lstm_persist<<<64, 256>>>();

    // 5: fused tgt GEMM + gates -> Hout fp16
    tgt_fused<<<dim3(G4 / 128, (T_ * B_) / 128), 256>>>();

    // 6-7: MLP (fp16 tensor cores)
    gemm_f16<1, 1><<<dim3(P1_ / 128, (T_ * B_) / 128), 256>>>(
        (const __half*)pHoutH, (const __half*)pW1h, b1, pZ1h, T_ * B_, P1_, H_);
    gemm_f16<1, 0><<<dim3(P2_ / 128, (T_ * B_) / 128), 256>>>(
        (const __half*)pZ1h, (const __half*)pW2h, b2, pZ2, T_ * B_, P2_, P1_);

    // 8: head + layout remap to (B, T)
    final_dot<<<(T_ * B_) / 8, 256>>>(W3, b3, out);
}

// round 9
// speedup vs baseline: 2.0087x; 1.1229x over previous
#include <cuda_runtime.h>
#include <cuda_fp16.h>
#include <math.h>
#include <stdint.h>

// Problem dims
#define B_   256
#define S_   200
#define T_   100
#define F_   10
#define E_   128
#define H_   256
#define G4   1024   // 4*H
#define P1_  512
#define P2_  128

// ---------------- scratch (device globals; no runtime alloc allowed) ----------------
__device__ __half g_eh  [S_*B_*E_];           // e fp16, [s][b][k]
__device__ __half g_Gxh [(size_t)T_*B_*G4];   // x-part+bias fp16, HIST ONLY, [s][b][n']
__device__ __half g_WihPh[G4*E_];             // permuted fp16 [n'][k]
__device__ float  g_WhhP[G4*H_];              // permuted fp32 [n'][k]
__device__ float  g_biasP[G4];
__device__ __half g_W1h[P1_*H_];              // [n][k] fp16
__device__ __half g_W2h[P2_*P1_];             // [n][k] fp16
__device__ float  g_c[B_*H_];                 // final cN [b][u]
__device__ float  g_r[B_*G4];                 // hN @ WhhP^T [b][n']
__device__ __half g_HoutH[T_*B_*H_];          // fp16
__device__ __half g_Z1h[(size_t)T_*B_*P1_];   // fp16
__device__ float  g_Z2[T_*B_*P2_];

// fast gate math (MUFU EX2 path); rel err ~1e-6, negligible vs budget
__device__ __forceinline__ float fsig(float x)
{
    return __fdividef(1.0f, 1.0f + __expf(-x));
}
__device__ __forceinline__ float ftanh(float x)
{
    return __fdividef(2.0f, 1.0f + __expf(-2.0f * x)) - 1.0f;
}

__device__ __forceinline__ void mma_f16(float* d, const uint32_t* a, const uint32_t* b)
{
    asm volatile(
        "mma.sync.aligned.m16n8k16.row.col.f32.f16.f16.f32 "
        "{%0,%1,%2,%3}, {%4,%5,%6,%7}, {%8,%9}, {%0,%1,%2,%3};\n"
        : "+f"(d[0]), "+f"(d[1]), "+f"(d[2]), "+f"(d[3])
        : "r"(a[0]), "r"(a[1]), "r"(a[2]), "r"(a[3]), "r"(b[0]), "r"(b[1]));
}

__device__ __forceinline__ void ldmx4(uint32_t* r, uint32_t addr)
{
    asm volatile(
        "ldmatrix.sync.aligned.m8n8.x4.shared.b16 {%0,%1,%2,%3}, [%4];\n"
        : "=r"(r[0]), "=r"(r[1]), "=r"(r[2]), "=r"(r[3]) : "r"(addr));
}

__device__ __forceinline__ uint32_t packh2(float lo, float hi)
{
    __half2 h = __floats2half2_rn(lo, hi);
    return *reinterpret_cast<uint32_t*>(&h);
}

// map local smem address into peer CTA's shared window
__device__ __forceinline__ uint32_t mapa_u32(uint32_t laddr, uint32_t rank)
{
    uint32_t r;
    asm volatile("mapa.shared::cluster.u32 %0, %1, %2;" : "=r"(r) : "r"(laddr), "r"(rank));
    return r;
}
__device__ __forceinline__ void st_dsmem16(uint32_t raddr, uint4 v)
{
    asm volatile("st.shared::cluster.v4.b32 [%0], {%1,%2,%3,%4};"
                 :: "r"(raddr), "r"(v.x), "r"(v.y), "r"(v.z), "r"(v.w) : "memory");
}

// swizzled offset for [rows][32 halfs] tiles, 16B units
__device__ __forceinline__ int swz16(int r, int u)
{
    return (r >> 1) * 128 + (((((r & 1) << 2) | u) ^ ((r >> 1) & 7)) << 4);
}

// ---------------- fused prep: permute + W1/W2 transpose (ONE launch) -----
__global__ void prep_all(const float* __restrict__ Wih, const float* __restrict__ Whh,
                         const float* __restrict__ bih, const float* __restrict__ bhh,
                         const float* __restrict__ W1,  const float* __restrict__ W2)
{
    int blk = blockIdx.x;
    int t   = threadIdx.x;
    if (blk < G4) {                               // permute LSTM weights
        int np  = blk;
        int src = (np & 3) * H_ + (np >> 2);
        if (t < E_) g_WihPh[np * E_ + t] = __float2half_rn(Wih[src * E_ + t]);
        g_WhhP[np * H_ + t] = Whh[src * H_ + t];
        if (t == 0) g_biasP[np] = bih[src] + bhh[src];
    } else if (blk < G4 + P1_) {                  // W1 (H,P1) -> [P1][H] fp16
        int n = blk - G4;
        g_W1h[n * H_ + t] = __float2half_rn(W1[t * P1_ + n]);
    } else {                                      // W2 (P1,P2) -> [P2][P1] fp16
        int n = blk - G4 - P1_;
        g_W2h[n * P1_ + t]       = __float2half_rn(W2[t * P2_ + n]);
        g_W2h[n * P1_ + t + 256] = __float2half_rn(W2[(t + 256) * P2_ + n]);
    }
}

__global__ void embed_mean(const int* __restrict__ x, const float* __restrict__ emb)
{
    int row = blockIdx.x;            // b*S_ + s
    int b = row / S_, s = row % S_;
    const int* xi = x + row * F_;
    int k = threadIdx.x;
    float sum = 0.0f;
#pragma unroll
    for (int f = 0; f < F_; f++) sum += emb[(size_t)xi[f] * E_ + k];
    g_eh[((size_t)s * B_ + b) * E_ + k] = __float2half_rn(sum * (1.0f / (float)F_));
}

// ---------------- fp16 tensor-core GEMM: C = act(A @ B^T + bias) ----------------
template<int RELU, int OUTH>
__global__ void __launch_bounds__(256) gemm_f16(const __half* __restrict__ A,
                                                const __half* __restrict__ Bh,
                                                const float* __restrict__ bias,
                                                void* __restrict__ Cv,
                                                int M, int N, int K)
{
    __shared__ __align__(16) __half As[128 * 32];
    __shared__ __align__(16) __half Bs[128 * 32];

    const int tid  = threadIdx.x;
    const int lane = tid & 31;
    const int warp = tid >> 5;
    const int g    = lane >> 2;
    const int q    = lane & 3;
    const int wm0  = (warp >> 2) << 6;
    const int wn0  = (warp & 3) << 5;
    const int m0   = blockIdx.y << 7;
    const int n0   = blockIdx.x << 7;

    const uint32_t As32 = (uint32_t)__cvta_generic_to_shared(As);
    const uint32_t Bs32 = (uint32_t)__cvta_generic_to_shared(Bs);

    const int lr = tid >> 2;
    const int lu = tid & 3;

    const __half* Ag0 = A  + (size_t)(m0 + lr) * K + lu * 8;
    const __half* Ag1 = Ag0 + (size_t)64 * K;
    const __half* Bg0 = Bh + (size_t)(n0 + lr) * K + lu * 8;
    const __half* Bg1 = Bg0 + (size_t)64 * K;

    float acc[4][4][4];
#pragma unroll
    for (int mi = 0; mi < 4; mi++)
#pragma unroll
        for (int ni = 0; ni < 4; ni++)
#pragma unroll
            for (int r = 0; r < 4; r++) acc[mi][ni][r] = 0.0f;

    uint4 pa0 = *(const uint4*)Ag0;
    uint4 pa1 = *(const uint4*)Ag1;
    uint4 pb0 = *(const uint4*)Bg0;
    uint4 pb1 = *(const uint4*)Bg1;

    const int nchunk = K >> 5;
    for (int ch = 0; ch < nchunk; ch++) {
        *(uint4*)((char*)As + swz16(lr,      lu)) = pa0;
        *(uint4*)((char*)As + swz16(lr + 64, lu)) = pa1;
        *(uint4*)((char*)Bs + swz16(lr,      lu)) = pb0;
        *(uint4*)((char*)Bs + swz16(lr + 64, lu)) = pb1;
        __syncthreads();

        if (ch + 1 < nchunk) {
            int ko = (ch + 1) << 5;
            pa0 = *(const uint4*)(Ag0 + ko);
            pa1 = *(const uint4*)(Ag1 + ko);
            pb0 = *(const uint4*)(Bg0 + ko);
            pb1 = *(const uint4*)(Bg1 + ko);
        }

#pragma unroll
        for (int ks = 0; ks < 2; ks++) {
            const int fu = ks * 2 + (lane >> 4);
            const int fr = lane & 15;
            uint32_t af[4][4], bf[4][2];
#pragma unroll
            for (int mt = 0; mt < 4; mt++)
                ldmx4(af[mt], As32 + swz16(wm0 + mt * 16 + fr, fu));
#pragma unroll
            for (int np = 0; np < 2; np++) {
                uint32_t t[4];
                ldmx4(t, Bs32 + swz16(wn0 + np * 16 + fr, fu));
                bf[2 * np][0]     = t[0];
                bf[2 * np + 1][0] = t[1];
                bf[2 * np][1]     = t[2];
                bf[2 * np + 1][1] = t[3];
            }
#pragma unroll
            for (int mt = 0; mt < 4; mt++)
#pragma unroll
                for (int nt = 0; nt < 4; nt++)
                    mma_f16(acc[mt][nt], af[mt], bf[nt]);
        }
        __syncthreads();
    }

#pragma unroll
    for (int nt = 0; nt < 4; nt++) {
        int cn = n0 + wn0 + nt * 8 + 2 * q;
        float bb0 = bias[cn], bb1 = bias[cn + 1];
#pragma unroll
        for (int mt = 0; mt < 4; mt++) {
            int r0 = m0 + wm0 + mt * 16 + g;
            float v0 = acc[mt][nt][0] + bb0;
            float v1 = acc[mt][nt][1] + bb1;
            float v2 = acc[mt][nt][2] + bb0;
            float v3 = acc[mt][nt][3] + bb1;
            if (RELU) {
                v0 = fmaxf(v0, 0.f); v1 = fmaxf(v1, 0.f);
                v2 = fmaxf(v2, 0.f); v3 = fmaxf(v3, 0.f);
            }
            if (OUTH) {
                __half* Ch = (__half*)Cv;
                *(__half2*)&Ch[(size_t)r0 * N + cn]       = __floats2half2_rn(v0, v1);
                *(__half2*)&Ch[(size_t)(r0 + 8) * N + cn] = __floats2half2_rn(v2, v3);
            } else {
                float* Cf = (float*)Cv;
                *(float2*)&Cf[(size_t)r0 * N + cn]       = make_float2(v0, v1);
                *(float2*)&Cf[(size_t)(r0 + 8) * N + cn] = make_float2(v2, v3);
            }
        }
    }
}

// ---------------- persistent fp16 LSTM: 8 clusters x 8 CTAs, DSMEM h-exchange -----
// Cluster = batch group of 32 rows; CTA = n' slice [rank*128,+128) -> units [rank*32,+32).
// h NEVER goes through global memory: each CTA writes its 2KB h-slice directly into
// ALL 8 peers' smem (mapa + st.shared::cluster) at the swizzled ldmatrix layout,
// double-buffered.  The cluster barrier orders the writes.  Next step's ldmatrix
// reads straight from local smem -> the entire global-fill phase is gone.
__global__ void __launch_bounds__(256, 1) __cluster_dims__(8, 1, 1) lstm_persist()
{
    __shared__ __align__(16) unsigned char Asm[2][32 * 512]; // h tile double buffer (32KB)
    __shared__ __align__(16) __half hstg[32 * 32];           // h slice staging (2KB)

    const int tid  = threadIdx.x;
    const int lane = tid & 31;
    const int warp = tid >> 5;
    const int g    = lane >> 2;
    const int q    = lane & 3;
    const int wn   = warp;                 // 8 warps x 16 n'
    const int grp  = blockIdx.x >> 3;      // batch group 0..7 (32 rows each)
    const int rank = blockIdx.x & 7;       // cluster rank = n' slice
    const int b0   = grp << 5;
    const int np0  = rank << 7;            // 128 n' per CTA
    const int u0   = rank << 5;            // 32 units per CTA

    const uint32_t asm_u32 = (uint32_t)__cvta_generic_to_shared(&Asm[0][0]);

    // zero buffer 0 (h0 = 0); peers' step-0 writes go to buffer 1 (disjoint)
#pragma unroll
    for (int it = 0; it < 4; it++)
        ((uint4*)&Asm[0][0])[tid + it * 256] = make_uint4(0, 0, 0, 0);

    // W fragments into registers (once): warp covers 16 n' (nt=2)
    uint32_t br[2][16][2];
#pragma unroll
    for (int nt = 0; nt < 2; nt++) {
        const int np = np0 + wn * 16 + nt * 8 + g;
        const float* wp = g_WhhP + (size_t)np * H_;
#pragma unroll
        for (int kc = 0; kc < 16; kc++) {
            float2 lo = *(const float2*)&wp[kc * 16 + 2 * q];
            float2 hi = *(const float2*)&wp[kc * 16 + 2 * q + 8];
            br[nt][kc][0] = packh2(lo.x, lo.y);
            br[nt][kc][1] = packh2(hi.x, hi.y);
        }
    }

    // ldmatrix addresses: 2 m-tiles cover the 32 batch rows
    uint32_t abase[2]; int axor[2];
#pragma unroll
    for (int mt = 0; mt < 2; mt++) {
        int ar = mt * 16 + (lane & 15);
        abase[mt] = asm_u32 + ar * 512;
        axor[mt]  = (ar & 7) << 4;
    }
    const int acol0 = (lane >> 4) * 16;

    // DSMEM write target (this thread's 16B unit of the CTA's h-slice), rank-invariant
    const int wrow = tid >> 2, wj = tid & 3;
    const int wcu  = rank * 4 + wj;        // 16B-unit column in the full 256-unit tile
    const uint32_t woff = wrow * 512 + ((wcu * 16) ^ ((wrow & 7) << 4));

    // cluster launch hygiene: everyone's smem initialized before cross-writes matter
    asm volatile("barrier.cluster.arrive.aligned;" ::: "memory");
    asm volatile("barrier.cluster.wait.aligned;" ::: "memory");

    float cst[2][2] = {{0.f, 0.f}, {0.f, 0.f}};

    for (int s = 0; s <= T_; s++) {
        const uint32_t bufoff = (uint32_t)(s & 1) * 16384;

        // Gx prefetch (fp16; overlaps the mma)
        __half2 gxv[2][2][2];
        if (s < T_) {
#pragma unroll
            for (int mt = 0; mt < 2; mt++)
#pragma unroll
                for (int nt = 0; nt < 2; nt++) {
                    const int bg = b0 + mt * 16 + g;
                    const int nc = np0 + wn * 16 + nt * 8 + 2 * q;
                    const __half* gp = g_Gxh + ((size_t)s * B_ + bg) * G4 + nc;
                    gxv[mt][nt][0] = *(const __half2*)gp;
                    gxv[mt][nt][1] = *(const __half2*)(gp + (size_t)8 * G4);
                }
        }

        // mma mainloop straight out of local smem (peers delivered h via DSMEM)
        float acc[2][2][4];
#pragma unroll
        for (int mt = 0; mt < 2; mt++)
#pragma unroll
            for (int nt = 0; nt < 2; nt++)
#pragma unroll
                for (int r = 0; r < 4; r++) acc[mt][nt][r] = 0.f;

#pragma unroll
        for (int kc = 0; kc < 16; kc++) {
            uint32_t af[2][4];
#pragma unroll
            for (int mt = 0; mt < 2; mt++)
                ldmx4(af[mt], abase[mt] + bufoff + ((acol0 + kc * 32) ^ axor[mt]));
#pragma unroll
            for (int mt = 0; mt < 2; mt++) {
                mma_f16(acc[mt][0], af[mt], br[0][kc]);
                mma_f16(acc[mt][1], af[mt], br[1][kc]);
            }
        }

        if (s < T_) {
            // gate epilogue -> smem staging
            const int hi = q & 1;
#pragma unroll
            for (int mt = 0; mt < 2; mt++)
#pragma unroll
                for (int nt = 0; nt < 2; nt++) {
                    float2 glo = __half22float2(gxv[mt][nt][0]);
                    float2 ghi = __half22float2(gxv[mt][nt][1]);
                    float p0 = acc[mt][nt][0] + glo.x;
                    float p1 = acc[mt][nt][1] + glo.y;
                    float p2 = acc[mt][nt][2] + ghi.x;
                    float p3 = acc[mt][nt][3] + ghi.y;
                    float r0 = __shfl_xor_sync(0xffffffffu, p0, 1);
                    float r1 = __shfl_xor_sync(0xffffffffu, p1, 1);
                    float r2 = __shfl_xor_sync(0xffffffffu, p2, 1);
                    float r3 = __shfl_xor_sync(0xffffffffu, p3, 1);
                    float gi = hi ? r2 : p0;
                    float gf = hi ? r3 : p1;
                    float gg = hi ? p2 : r0;
                    float go = hi ? p3 : r1;
                    float c  = fsig(gf) * cst[mt][nt] + fsig(gi) * ftanh(gg);
                    cst[mt][nt] = c;
                    float h  = fsig(go) * ftanh(c);
                    const int bl = mt * 16 + g + (hi ? 8 : 0);
                    const int ul = wn * 4 + nt * 2 + (q >> 1);
                    hstg[bl * 32 + ul] = __float2half_rn(h);
                }
            __syncthreads();

            // broadcast this CTA's h-slice to ALL 8 cluster CTAs' next buffer (DSMEM)
            if (tid < 128) {
                uint4 v = *(uint4*)&hstg[wrow * 32 + wj * 8];
                uint32_t dst = asm_u32 + (bufoff ^ 16384u) + woff;
#pragma unroll
                for (uint32_t pr = 0; pr < 8; pr++)
                    st_dsmem16(mapa_u32(dst, pr), v);
            }

            // ONE hw cluster barrier: orders DSMEM writes, releases next step
            asm volatile("barrier.cluster.arrive.aligned;" ::: "memory");
            asm volatile("barrier.cluster.wait.aligned;" ::: "memory");
        } else {
            // s == T_: export r = hN @ W^T and cN
            const int hi = q & 1;
#pragma unroll
            for (int mt = 0; mt < 2; mt++)
#pragma unroll
                for (int nt = 0; nt < 2; nt++) {
                    const int m_lo = b0 + mt * 16 + g;
                    const int nc = np0 + wn * 16 + nt * 8 + 2 * q;
                    *(float2*)&g_r[(size_t)m_lo * G4 + nc] =
                        make_float2(acc[mt][nt][0], acc[mt][nt][1]);
                    *(float2*)&g_r[(size_t)(m_lo + 8) * G4 + nc] =
                        make_float2(acc[mt][nt][2], acc[mt][nt][3]);
                    const int b = m_lo + (hi ? 8 : 0);
                    const int u = u0 + wn * 4 + nt * 2 + (q >> 1);
                    g_c[(size_t)b * H_ + u] = cst[mt][nt];
                }
        }
    }

    // final cluster barrier: no CTA exits while peers' DSMEM writes could be in flight
    asm volatile("barrier.cluster.arrive.aligned;" ::: "memory");
    asm volatile("barrier.cluster.wait.aligned;" ::: "memory");
}

// ---------------- fused tgt kernel: gates(e_tgt @ WihP^T + bias + r[b]) -> Hout fp16 ----
__global__ void __launch_bounds__(256) tgt_fused()
{
    __shared__ __align__(16) __half As[128 * 32];
    __shared__ __align__(16) __half Bs[128 * 32];

    const int tid  = threadIdx.x;
    const int lane = tid & 31;
    const int warp = tid >> 5;
    const int g    = lane >> 2;
    const int q    = lane & 3;
    const int wm0  = (warp >> 2) << 6;
    const int wn0  = (warp & 3) << 5;
    const int m0   = blockIdx.y << 7;
    const int n0   = blockIdx.x << 7;

    const uint32_t As32 = (uint32_t)__cvta_generic_to_shared(As);
    const uint32_t Bs32 = (uint32_t)__cvta_generic_to_shared(Bs);

    const int lr = tid >> 2;
    const int lu = tid & 3;

    const __half* A = g_eh + (size_t)T_ * B_ * E_;   // tgt rows
    const __half* Ag0 = A + (size_t)(m0 + lr) * E_ + lu * 8;
    const __half* Ag1 = Ag0 + (size_t)64 * E_;
    const __half* Bg0 = g_WihPh + (size_t)(n0 + lr) * E_ + lu * 8;
    const __half* Bg1 = Bg0 + (size_t)64 * E_;

    float acc[4][4][4];
#pragma unroll
    for (int mi = 0; mi < 4; mi++)
#pragma unroll
        for (int ni = 0; ni < 4; ni++)
#pragma unroll
            for (int r = 0; r < 4; r++) acc[mi][ni][r] = 0.0f;

    uint4 pa0 = *(const uint4*)Ag0;
    uint4 pa1 = *(const uint4*)Ag1;
    uint4 pb0 = *(const uint4*)Bg0;
    uint4 pb1 = *(const uint4*)Bg1;

    const int nchunk = E_ >> 5;   // 4
    for (int ch = 0; ch < nchunk; ch++) {
        *(uint4*)((char*)As + swz16(lr,      lu)) = pa0;
        *(uint4*)((char*)As + swz16(lr + 64, lu)) = pa1;
        *(uint4*)((char*)Bs + swz16(lr,      lu)) = pb0;
        *(uint4*)((char*)Bs + swz16(lr + 64, lu)) = pb1;
        __syncthreads();

        if (ch + 1 < nchunk) {
            int ko = (ch + 1) << 5;
            pa0 = *(const uint4*)(Ag0 + ko);
            pa1 = *(const uint4*)(Ag1 + ko);
            pb0 = *(const uint4*)(Bg0 + ko);
            pb1 = *(const uint4*)(Bg1 + ko);
        }

#pragma unroll
        for (int ks = 0; ks < 2; ks++) {
            const int fu = ks * 2 + (lane >> 4);
            const int fr = lane & 15;
            uint32_t af[4][4], bf[4][2];
#pragma unroll
            for (int mt = 0; mt < 4; mt++)
                ldmx4(af[mt], As32 + swz16(wm0 + mt * 16 + fr, fu));
#pragma unroll
            for (int np = 0; np < 2; np++) {
                uint32_t t[4];
                ldmx4(t, Bs32 + swz16(wn0 + np * 16 + fr, fu));
                bf[2 * np][0]     = t[0];
                bf[2 * np + 1][0] = t[1];
                bf[2 * np][1]     = t[2];
                bf[2 * np + 1][1] = t[3];
            }
#pragma unroll
            for (int mt = 0; mt < 4; mt++)
#pragma unroll
                for (int nt = 0; nt < 4; nt++)
                    mma_f16(acc[mt][nt], af[mt], bf[nt]);
        }
        __syncthreads();
    }

    // fast gate epilogue
    const int hi = q & 1;
#pragma unroll
    for (int nt = 0; nt < 4; nt++) {
        const int cn = n0 + wn0 + nt * 8 + 2 * q;
        const float bb0 = g_biasP[cn], bb1 = g_biasP[cn + 1];
        const int u = ((n0 + wn0 + nt * 8) >> 2) + (q >> 1);
#pragma unroll
        for (int mt = 0; mt < 4; mt++) {
            const int m_lo = m0 + wm0 + mt * 16 + g;
            const int m_hi = m_lo + 8;
            float2 rlo = *(const float2*)&g_r[(size_t)(m_lo & 255) * G4 + cn];
            float2 rhi = *(const float2*)&g_r[(size_t)(m_hi & 255) * G4 + cn];
            float p0 = acc[mt][nt][0] + bb0 + rlo.x;
            float p1 = acc[mt][nt][1] + bb1 + rlo.y;
            float p2 = acc[mt][nt][2] + bb0 + rhi.x;
            float p3 = acc[mt][nt][3] + bb1 + rhi.y;
            float r0 = __shfl_xor_sync(0xffffffffu, p0, 1);
            float r1 = __shfl_xor_sync(0xffffffffu, p1, 1);
            float r2 = __shfl_xor_sync(0xffffffffu, p2, 1);
            float r3 = __shfl_xor_sync(0xffffffffu, p3, 1);
            float gi = hi ? r2 : p0;
            float gf = hi ? r3 : p1;
            float gg = hi ? p2 : r0;
            float go = hi ? p3 : r1;
            const int m_sel = hi ? m_hi : m_lo;
            const int b_sel = m_sel & 255;
            float cprev = g_c[(size_t)b_sel * H_ + u];
            float c = fsig(gf) * cprev + fsig(gi) * ftanh(gg);
            float h = fsig(go) * ftanh(c);
            g_HoutH[(size_t)m_sel * H_ + u] = __float2half_rn(h);
        }
    }
}

// ---------------- final: out = sigmoid(Z2 @ W3 + b3), remap (t,b) -> (b,t) ----------------
__global__ void final_dot(const float* __restrict__ W3, const float* __restrict__ b3,
                          float* __restrict__ out)
{
    int row  = blockIdx.x * 8 + (threadIdx.x >> 5);
    int lane = threadIdx.x & 31;
    float4 z = *(const float4*)&g_Z2[row * P2_ + lane * 4];
    float4 w = *(const float4*)&W3[lane * 4];
    float s = z.x * w.x + z.y * w.y + z.z * w.z + z.w * w.w;
#pragma unroll
    for (int o = 16; o > 0; o >>= 1) s += __shfl_xor_sync(0xffffffffu, s, o);
    if (lane == 0) {
        int tt = row >> 8, b = row & 255;
        out[b * T_ + tt] = fsig(s + b3[0]);
    }
}

// ---------------- launcher ----------------
extern "C" void kernel_launch(void* const* d_in, const int* in_sizes, int n_in,
                              void* d_out, int out_size)
{
    const int*   x    = (const int*)  d_in[0];
    const float* emb  = (const float*)d_in[1];
    const float* Wih  = (const float*)d_in[2];
    const float* Whh  = (const float*)d_in[3];
    const float* bih  = (const float*)d_in[4];
    const float* bhh  = (const float*)d_in[5];
    const float* W1   = (const float*)d_in[6];
    const float* b1   = (const float*)d_in[7];
    const float* W2   = (const float*)d_in[8];
    const float* b2   = (const float*)d_in[9];
    const float* W3   = (const float*)d_in[10];
    const float* b3   = (const float*)d_in[11];
    float* out = (float*)d_out;

    void *peh, *pGxh, *pWihPh, *pbias, *pHoutH, *pZ1h, *pZ2, *pW1h, *pW2h;
    cudaGetSymbolAddress(&peh,    g_eh);
    cudaGetSymbolAddress(&pGxh,   g_Gxh);
    cudaGetSymbolAddress(&pWihPh, g_WihPh);
    cudaGetSymbolAddress(&pbias,  g_biasP);
    cudaGetSymbolAddress(&pHoutH, g_HoutH);
    cudaGetSymbolAddress(&pZ1h,   g_Z1h);
    cudaGetSymbolAddress(&pZ2,    g_Z2);
    cudaGetSymbolAddress(&pW1h,   g_W1h);
    cudaGetSymbolAddress(&pW2h,   g_W2h);

    // 1: fused prep (permute + W1/W2 transpose)
    prep_all<<<G4 + P1_ + P2_, 256>>>(Wih, Whh, bih, bhh, W1, W2);

    // 2: embedding mean
    embed_mean<<<B_ * S_, E_>>>(x, emb);

    // 3: x-part for HIST positions (fp16 out, bias folded)
    gemm_f16<0, 1><<<dim3(G4 / 128, (T_ * B_) / 128), 256>>>(
        (const __half*)peh, (const __half*)pWihPh, (const float*)pbias, pGxh,
        T_ * B_, G4, E_);

    // 4 (PROFILED): all 100 LSTM steps + r = hN@W, DSMEM-clustered persistent kernel
    lstm_persist<<<64, 256>>>();

    // 5: fused tgt GEMM + gates -> Hout fp16
    tgt_fused<<<dim3(G4 / 128, (T_ * B_) / 128), 256>>>();

    // 6-7: MLP (fp16 tensor cores)
    gemm_f16<1, 1><<<dim3(P1_ / 128, (T_ * B_) / 128), 256>>>(
        (const __half*)pHoutH, (const __half*)pW1h, b1, pZ1h, T_ * B_, P1_, H_);
    gemm_f16<1, 0><<<dim3(P2_ / 128, (T_ * B_) / 128), 256>>>(
        (const __half*)pZ1h, (const __half*)pW2h, b2, pZ2, T_ * B_, P2_, P1_);

    // 8: head + layout remap to (B, T)
    final_dot<<<(T_ * B_) / 8, 256>>>(W3, b3, out);
}

// round 10
// speedup vs baseline: 2.1491x; 1.0699x over previous
#include <cuda_runtime.h>
#include <cuda_fp16.h>
#include <math.h>
#include <stdint.h>

// Problem dims
#define B_   256
#define S_   200
#define T_   100
#define F_   10
#define E_   128
#define H_   256
#define G4   1024   // 4*H
#define P1_  512
#define P2_  128

// ---------------- scratch (device globals; no runtime alloc allowed) ----------------
__device__ __half g_eh  [S_*B_*E_];           // e fp16, [s][b][k]
__device__ __half g_Gxh [(size_t)T_*B_*G4];   // x-part+bias fp16, HIST ONLY, [s][b][n']
__device__ __half g_WihPh[G4*E_];             // permuted fp16 [n'][k]
__device__ float  g_WhhP[G4*H_];              // permuted fp32 [n'][k]
__device__ float  g_biasP[G4];
__device__ __half g_W1h[P1_*H_];              // [n][k] fp16
__device__ __half g_W2h[P2_*P1_];             // [n][k] fp16
__device__ float  g_c[B_*H_];                 // final cN [b][u]
__device__ float  g_r[B_*G4];                 // hN @ WhhP^T [b][n']
__device__ __half g_HoutH[T_*B_*H_];          // fp16
__device__ __half g_Z1h[(size_t)T_*B_*P1_];   // fp16
__device__ float  g_Z2[T_*B_*P2_];

// fast gate math (MUFU EX2 path); rel err ~1e-6, negligible vs budget
__device__ __forceinline__ float fsig(float x)
{
    return __fdividef(1.0f, 1.0f + __expf(-x));
}
__device__ __forceinline__ float ftanh(float x)
{
    return __fdividef(2.0f, 1.0f + __expf(-2.0f * x)) - 1.0f;
}

__device__ __forceinline__ void mma_f16(float* d, const uint32_t* a, const uint32_t* b)
{
    asm volatile(
        "mma.sync.aligned.m16n8k16.row.col.f32.f16.f16.f32 "
        "{%0,%1,%2,%3}, {%4,%5,%6,%7}, {%8,%9}, {%0,%1,%2,%3};\n"
        : "+f"(d[0]), "+f"(d[1]), "+f"(d[2]), "+f"(d[3])
        : "r"(a[0]), "r"(a[1]), "r"(a[2]), "r"(a[3]), "r"(b[0]), "r"(b[1]));
}

__device__ __forceinline__ void ldmx4(uint32_t* r, uint32_t addr)
{
    asm volatile(
        "ldmatrix.sync.aligned.m8n8.x4.shared.b16 {%0,%1,%2,%3}, [%4];\n"
        : "=r"(r[0]), "=r"(r[1]), "=r"(r[2]), "=r"(r[3]) : "r"(addr));
}

__device__ __forceinline__ uint32_t packh2(float lo, float hi)
{
    __half2 h = __floats2half2_rn(lo, hi);
    return *reinterpret_cast<uint32_t*>(&h);
}

// map local smem address into peer CTA's shared window
__device__ __forceinline__ uint32_t mapa_u32(uint32_t laddr, uint32_t rank)
{
    uint32_t r;
    asm volatile("mapa.shared::cluster.u32 %0, %1, %2;" : "=r"(r) : "r"(laddr), "r"(rank));
    return r;
}

// async remote store: 16B to peer smem, signals peer mbarrier with 16B tx
__device__ __forceinline__ void st_async16(uint32_t raddr, uint4 v, uint32_t rmbar)
{
    asm volatile(
        "st.async.shared::cluster.mbarrier::complete_tx::bytes.v4.b32 "
        "[%0], {%1,%2,%3,%4}, [%5];"
        :: "r"(raddr), "r"(v.x), "r"(v.y), "r"(v.z), "r"(v.w), "r"(rmbar) : "memory");
}

__device__ __forceinline__ void mbar_init(uint32_t mbar, uint32_t cnt)
{
    asm volatile("mbarrier.init.shared.b64 [%0], %1;" :: "r"(mbar), "r"(cnt) : "memory");
}
__device__ __forceinline__ void mbar_expect(uint32_t mbar, uint32_t bytes)
{
    asm volatile("mbarrier.arrive.expect_tx.shared.b64 _, [%0], %1;"
                 :: "r"(mbar), "r"(bytes) : "memory");
}
__device__ __forceinline__ void mbar_wait(uint32_t mbar, uint32_t parity)
{
    uint32_t done;
    asm volatile(
        "{\n\t.reg .pred p;\n\t"
        "mbarrier.try_wait.parity.acquire.cta.shared::cta.b64 p, [%1], %2;\n\t"
        "selp.b32 %0, 1, 0, p;\n\t}"
        : "=r"(done) : "r"(mbar), "r"(parity) : "memory");
    if (!done) {
        asm volatile(
            "{\n\t.reg .pred P1;\n\t"
            "WL_%=:\n\t"
            "mbarrier.try_wait.parity.acquire.cta.shared::cta.b64 P1, [%0], %1, 0x989680;\n\t"
            "@P1 bra.uni WD_%=;\n\t"
            "bra.uni WL_%=;\n\t"
            "WD_%=:\n\t}"
            :: "r"(mbar), "r"(parity) : "memory");
    }
}

// swizzled offset for [rows][32 halfs] tiles, 16B units
__device__ __forceinline__ int swz16(int r, int u)
{
    return (r >> 1) * 128 + (((((r & 1) << 2) | u) ^ ((r >> 1) & 7)) << 4);
}

// ---------------- fused prep: permute + W1/W2 transpose (ONE launch) -----
__global__ void prep_all(const float* __restrict__ Wih, const float* __restrict__ Whh,
                         const float* __restrict__ bih, const float* __restrict__ bhh,
                         const float* __restrict__ W1,  const float* __restrict__ W2)
{
    int blk = blockIdx.x;
    int t   = threadIdx.x;
    if (blk < G4) {                               // permute LSTM weights
        int np  = blk;
        int src = (np & 3) * H_ + (np >> 2);
        if (t < E_) g_WihPh[np * E_ + t] = __float2half_rn(Wih[src * E_ + t]);
        g_WhhP[np * H_ + t] = Whh[src * H_ + t];
        if (t == 0) g_biasP[np] = bih[src] + bhh[src];
    } else if (blk < G4 + P1_) {                  // W1 (H,P1) -> [P1][H] fp16
        int n = blk - G4;
        g_W1h[n * H_ + t] = __float2half_rn(W1[t * P1_ + n]);
    } else {                                      // W2 (P1,P2) -> [P2][P1] fp16
        int n = blk - G4 - P1_;
        g_W2h[n * P1_ + t]       = __float2half_rn(W2[t * P2_ + n]);
        g_W2h[n * P1_ + t + 256] = __float2half_rn(W2[(t + 256) * P2_ + n]);
    }
}

__global__ void embed_mean(const int* __restrict__ x, const float* __restrict__ emb)
{
    int row = blockIdx.x;            // b*S_ + s
    int b = row / S_, s = row % S_;
    const int* xi = x + row * F_;
    int k = threadIdx.x;
    float sum = 0.0f;
#pragma unroll
    for (int f = 0; f < F_; f++) sum += emb[(size_t)xi[f] * E_ + k];
    g_eh[((size_t)s * B_ + b) * E_ + k] = __float2half_rn(sum * (1.0f / (float)F_));
}

// ---------------- fp16 tensor-core GEMM: C = act(A @ B^T + bias) ----------------
template<int RELU, int OUTH>
__global__ void __launch_bounds__(256) gemm_f16(const __half* __restrict__ A,
                                                const __half* __restrict__ Bh,
                                                const float* __restrict__ bias,
                                                void* __restrict__ Cv,
                                                int M, int N, int K)
{
    __shared__ __align__(16) __half As[128 * 32];
    __shared__ __align__(16) __half Bs[128 * 32];

    const int tid  = threadIdx.x;
    const int lane = tid & 31;
    const int warp = tid >> 5;
    const int g    = lane >> 2;
    const int q    = lane & 3;
    const int wm0  = (warp >> 2) << 6;
    const int wn0  = (warp & 3) << 5;
    const int m0   = blockIdx.y << 7;
    const int n0   = blockIdx.x << 7;

    const uint32_t As32 = (uint32_t)__cvta_generic_to_shared(As);
    const uint32_t Bs32 = (uint32_t)__cvta_generic_to_shared(Bs);

    const int lr = tid >> 2;
    const int lu = tid & 3;

    const __half* Ag0 = A  + (size_t)(m0 + lr) * K + lu * 8;
    const __half* Ag1 = Ag0 + (size_t)64 * K;
    const __half* Bg0 = Bh + (size_t)(n0 + lr) * K + lu * 8;
    const __half* Bg1 = Bg0 + (size_t)64 * K;

    float acc[4][4][4];
#pragma unroll
    for (int mi = 0; mi < 4; mi++)
#pragma unroll
        for (int ni = 0; ni < 4; ni++)
#pragma unroll
            for (int r = 0; r < 4; r++) acc[mi][ni][r] = 0.0f;

    uint4 pa0 = *(const uint4*)Ag0;
    uint4 pa1 = *(const uint4*)Ag1;
    uint4 pb0 = *(const uint4*)Bg0;
    uint4 pb1 = *(const uint4*)Bg1;

    const int nchunk = K >> 5;
    for (int ch = 0; ch < nchunk; ch++) {
        *(uint4*)((char*)As + swz16(lr,      lu)) = pa0;
        *(uint4*)((char*)As + swz16(lr + 64, lu)) = pa1;
        *(uint4*)((char*)Bs + swz16(lr,      lu)) = pb0;
        *(uint4*)((char*)Bs + swz16(lr + 64, lu)) = pb1;
        __syncthreads();

        if (ch + 1 < nchunk) {
            int ko = (ch + 1) << 5;
            pa0 = *(const uint4*)(Ag0 + ko);
            pa1 = *(const uint4*)(Ag1 + ko);
            pb0 = *(const uint4*)(Bg0 + ko);
            pb1 = *(const uint4*)(Bg1 + ko);
        }

#pragma unroll
        for (int ks = 0; ks < 2; ks++) {
            const int fu = ks * 2 + (lane >> 4);
            const int fr = lane & 15;
            uint32_t af[4][4], bf[4][2];
#pragma unroll
            for (int mt = 0; mt < 4; mt++)
                ldmx4(af[mt], As32 + swz16(wm0 + mt * 16 + fr, fu));
#pragma unroll
            for (int np = 0; np < 2; np++) {
                uint32_t t[4];
                ldmx4(t, Bs32 + swz16(wn0 + np * 16 + fr, fu));
                bf[2 * np][0]     = t[0];
                bf[2 * np + 1][0] = t[1];
                bf[2 * np][1]     = t[2];
                bf[2 * np + 1][1] = t[3];
            }
#pragma unroll
            for (int mt = 0; mt < 4; mt++)
#pragma unroll
                for (int nt = 0; nt < 4; nt++)
                    mma_f16(acc[mt][nt], af[mt], bf[nt]);
        }
        __syncthreads();
    }

#pragma unroll
    for (int nt = 0; nt < 4; nt++) {
        int cn = n0 + wn0 + nt * 8 + 2 * q;
        float bb0 = bias[cn], bb1 = bias[cn + 1];
#pragma unroll
        for (int mt = 0; mt < 4; mt++) {
            int r0 = m0 + wm0 + mt * 16 + g;
            float v0 = acc[mt][nt][0] + bb0;
            float v1 = acc[mt][nt][1] + bb1;
            float v2 = acc[mt][nt][2] + bb0;
            float v3 = acc[mt][nt][3] + bb1;
            if (RELU) {
                v0 = fmaxf(v0, 0.f); v1 = fmaxf(v1, 0.f);
                v2 = fmaxf(v2, 0.f); v3 = fmaxf(v3, 0.f);
            }
            if (OUTH) {
                __half* Ch = (__half*)Cv;
                *(__half2*)&Ch[(size_t)r0 * N + cn]       = __floats2half2_rn(v0, v1);
                *(__half2*)&Ch[(size_t)(r0 + 8) * N + cn] = __floats2half2_rn(v2, v3);
            } else {
                float* Cf = (float*)Cv;
                *(float2*)&Cf[(size_t)r0 * N + cn]       = make_float2(v0, v1);
                *(float2*)&Cf[(size_t)(r0 + 8) * N + cn] = make_float2(v2, v3);
            }
        }
    }
}

// ---------------- persistent fp16 LSTM: 8 clusters x 8 CTAs, st.async + mbarrier -----
// Cluster = batch group of 32 rows; CTA = n' slice [rank*128,+128) -> units [rank*32,+32).
// h-exchange: each CTA st.async's its 2KB slice into all 8 peers' double-buffered
// swizzled tile, signaling each peer's buffer mbarrier (complete_tx).  Each CTA waits
// ONLY on its own inbox mbar (try_wait.parity.acquire, ~60-90cyc) — no cluster.sync
// per step, no L1D flush, no full-cluster rendezvous.  Backpressure is implied by the
// all-to-all dependency (peer can't reach step s+2's writes before consuming my s+1).
__global__ void __launch_bounds__(256, 1) __cluster_dims__(8, 1, 1) lstm_persist()
{
    __shared__ __align__(16) unsigned char Asm[2][32 * 512]; // h tile double buffer (32KB)
    __shared__ __align__(16) __half hstg[32 * 32];           // h slice staging (2KB)
    __shared__ __align__(8)  uint64_t mbar_s[2];             // inbox mbarriers (per buffer)

    const int tid  = threadIdx.x;
    const int lane = tid & 31;
    const int warp = tid >> 5;
    const int g    = lane >> 2;
    const int q    = lane & 3;
    const int wn   = warp;                 // 8 warps x 16 n'
    const int grp  = blockIdx.x >> 3;      // batch group 0..7 (32 rows each)
    const int rank = blockIdx.x & 7;       // cluster rank = n' slice
    const int b0   = grp << 5;
    const int np0  = rank << 7;            // 128 n' per CTA
    const int u0   = rank << 5;            // 32 units per CTA

    const uint32_t asm_u32  = (uint32_t)__cvta_generic_to_shared(&Asm[0][0]);
    const uint32_t mbar_u32 = (uint32_t)__cvta_generic_to_shared(&mbar_s[0]);

    // zero buffer 0 (h0 = 0); peers' step-0 writes go to buffer 1 (disjoint)
#pragma unroll
    for (int it = 0; it < 4; it++)
        ((uint4*)&Asm[0][0])[tid + it * 256] = make_uint4(0, 0, 0, 0);

    // init inbox mbarriers (count=1: the local expect_tx arrival per phase)
    if (tid == 0) {
        mbar_init(mbar_u32,     1);
        mbar_init(mbar_u32 + 8, 1);
    }
    __syncthreads();

    // W fragments into registers (once): warp covers 16 n' (nt=2)
    uint32_t br[2][16][2];
#pragma unroll
    for (int nt = 0; nt < 2; nt++) {
        const int np = np0 + wn * 16 + nt * 8 + g;
        const float* wp = g_WhhP + (size_t)np * H_;
#pragma unroll
        for (int kc = 0; kc < 16; kc++) {
            float2 lo = *(const float2*)&wp[kc * 16 + 2 * q];
            float2 hi = *(const float2*)&wp[kc * 16 + 2 * q + 8];
            br[nt][kc][0] = packh2(lo.x, lo.y);
            br[nt][kc][1] = packh2(hi.x, hi.y);
        }
    }

    // ldmatrix addresses: 2 m-tiles cover the 32 batch rows
    uint32_t abase[2]; int axor[2];
#pragma unroll
    for (int mt = 0; mt < 2; mt++) {
        int ar = mt * 16 + (lane & 15);
        abase[mt] = asm_u32 + ar * 512;
        axor[mt]  = (ar & 7) << 4;
    }
    const int acol0 = (lane >> 4) * 16;

    // DSMEM write target (this thread's 16B unit of the CTA's h-slice), rank-invariant
    const int wrow = tid >> 2, wj = tid & 3;
    const int wcu  = rank * 4 + wj;        // 16B-unit column in the full 256-unit tile
    const uint32_t woff = wrow * 512 + ((wcu * 16) ^ ((wrow & 7) << 4));

    // cluster hygiene: all peers' mbarriers and buffers initialized before any st.async
    asm volatile("barrier.cluster.arrive.aligned;" ::: "memory");
    asm volatile("barrier.cluster.wait.aligned;" ::: "memory");

    float cst[2][2] = {{0.f, 0.f}, {0.f, 0.f}};
    uint32_t ph[2] = {0, 0};               // parity tracker per inbox mbar

    for (int s = 0; s <= T_; s++) {
        const uint32_t bufoff = (uint32_t)(s & 1) * 16384;

        // wait for this step's inbox (s=0 reads the locally-zeroed buffer)
        if (s > 0) {
            mbar_wait(mbar_u32 + (uint32_t)(s & 1) * 8, ph[s & 1]);
            ph[s & 1] ^= 1;
        }

        // Gx prefetch (fp16; overlaps the mma)
        __half2 gxv[2][2][2];
        if (s < T_) {
#pragma unroll
            for (int mt = 0; mt < 2; mt++)
#pragma unroll
                for (int nt = 0; nt < 2; nt++) {
                    const int bg = b0 + mt * 16 + g;
                    const int nc = np0 + wn * 16 + nt * 8 + 2 * q;
                    const __half* gp = g_Gxh + ((size_t)s * B_ + bg) * G4 + nc;
                    gxv[mt][nt][0] = *(const __half2*)gp;
                    gxv[mt][nt][1] = *(const __half2*)(gp + (size_t)8 * G4);
                }
        }

        // mma mainloop straight out of local smem
        float acc[2][2][4];
#pragma unroll
        for (int mt = 0; mt < 2; mt++)
#pragma unroll
            for (int nt = 0; nt < 2; nt++)
#pragma unroll
                for (int r = 0; r < 4; r++) acc[mt][nt][r] = 0.f;

#pragma unroll
        for (int kc = 0; kc < 16; kc++) {
            uint32_t af[2][4];
#pragma unroll
            for (int mt = 0; mt < 2; mt++)
                ldmx4(af[mt], abase[mt] + bufoff + ((acol0 + kc * 32) ^ axor[mt]));
#pragma unroll
            for (int mt = 0; mt < 2; mt++) {
                mma_f16(acc[mt][0], af[mt], br[0][kc]);
                mma_f16(acc[mt][1], af[mt], br[1][kc]);
            }
        }

        if (s < T_) {
            // gate epilogue -> smem staging
            const int hi = q & 1;
#pragma unroll
            for (int mt = 0; mt < 2; mt++)
#pragma unroll
                for (int nt = 0; nt < 2; nt++) {
                    float2 glo = __half22float2(gxv[mt][nt][0]);
                    float2 ghi = __half22float2(gxv[mt][nt][1]);
                    float p0 = acc[mt][nt][0] + glo.x;
                    float p1 = acc[mt][nt][1] + glo.y;
                    float p2 = acc[mt][nt][2] + ghi.x;
                    float p3 = acc[mt][nt][3] + ghi.y;
                    float r0 = __shfl_xor_sync(0xffffffffu, p0, 1);
                    float r1 = __shfl_xor_sync(0xffffffffu, p1, 1);
                    float r2 = __shfl_xor_sync(0xffffffffu, p2, 1);
                    float r3 = __shfl_xor_sync(0xffffffffu, p3, 1);
                    float gi = hi ? r2 : p0;
                    float gf = hi ? r3 : p1;
                    float gg = hi ? p2 : r0;
                    float go = hi ? p3 : r1;
                    float c  = fsig(gf) * cst[mt][nt] + fsig(gi) * ftanh(gg);
                    cst[mt][nt] = c;
                    float h  = fsig(go) * ftanh(c);
                    const int bl = mt * 16 + g + (hi ? 8 : 0);
                    const int ul = wn * 4 + nt * 2 + (q >> 1);
                    hstg[bl * 32 + ul] = __float2half_rn(h);
                }
            __syncthreads();

            // register local expect for next step's inbox, then broadcast slice
            const uint32_t nb = (uint32_t)((s + 1) & 1);
            if (tid == 0) mbar_expect(mbar_u32 + nb * 8, 16384u);
            if (tid < 128) {
                uint4 v = *(uint4*)&hstg[wrow * 32 + wj * 8];
                const uint32_t dsto = asm_u32 + (bufoff ^ 16384u) + woff;
                const uint32_t mbo  = mbar_u32 + nb * 8;
#pragma unroll
                for (uint32_t pr = 0; pr < 8; pr++)
                    st_async16(mapa_u32(dsto, pr), v, mapa_u32(mbo, pr));
            }
            // no cluster barrier: next step's mbar_wait provides the ordering
        } else {
            // s == T_: export r = hN @ W^T and cN
            const int hi = q & 1;
#pragma unroll
            for (int mt = 0; mt < 2; mt++)
#pragma unroll
                for (int nt = 0; nt < 2; nt++) {
                    const int m_lo = b0 + mt * 16 + g;
                    const int nc = np0 + wn * 16 + nt * 8 + 2 * q;
                    *(float2*)&g_r[(size_t)m_lo * G4 + nc] =
                        make_float2(acc[mt][nt][0], acc[mt][nt][1]);
                    *(float2*)&g_r[(size_t)(m_lo + 8) * G4 + nc] =
                        make_float2(acc[mt][nt][2], acc[mt][nt][3]);
                    const int b = m_lo + (hi ? 8 : 0);
                    const int u = u0 + wn * 4 + nt * 2 + (q >> 1);
                    g_c[(size_t)b * H_ + u] = cst[mt][nt];
                }
        }
    }

    // final cluster barrier: no CTA exits while peers' async stores could be in flight
    asm volatile("barrier.cluster.arrive.aligned;" ::: "memory");
    asm volatile("barrier.cluster.wait.aligned;" ::: "memory");
}

// ---------------- fused tgt kernel: gates(e_tgt @ WihP^T + bias + r[b]) -> Hout fp16 ----
__global__ void __launch_bounds__(256) tgt_fused()
{
    __shared__ __align__(16) __half As[128 * 32];
    __shared__ __align__(16) __half Bs[128 * 32];

    const int tid  = threadIdx.x;
    const int lane = tid & 31;
    const int warp = tid >> 5;
    const int g    = lane >> 2;
    const int q    = lane & 3;
    const int wm0  = (warp >> 2) << 6;
    const int wn0  = (warp & 3) << 5;
    const int m0   = blockIdx.y << 7;
    const int n0   = blockIdx.x << 7;

    const uint32_t As32 = (uint32_t)__cvta_generic_to_shared(As);
    const uint32_t Bs32 = (uint32_t)__cvta_generic_to_shared(Bs);

    const int lr = tid >> 2;
    const int lu = tid & 3;

    const __half* A = g_eh + (size_t)T_ * B_ * E_;   // tgt rows
    const __half* Ag0 = A + (size_t)(m0 + lr) * E_ + lu * 8;
    const __half* Ag1 = Ag0 + (size_t)64 * E_;
    const __half* Bg0 = g_WihPh + (size_t)(n0 + lr) * E_ + lu * 8;
    const __half* Bg1 = Bg0 + (size_t)64 * E_;

    float acc[4][4][4];
#pragma unroll
    for (int mi = 0; mi < 4; mi++)
#pragma unroll
        for (int ni = 0; ni < 4; ni++)
#pragma unroll
            for (int r = 0; r < 4; r++) acc[mi][ni][r] = 0.0f;

    uint4 pa0 = *(const uint4*)Ag0;
    uint4 pa1 = *(const uint4*)Ag1;
    uint4 pb0 = *(const uint4*)Bg0;
    uint4 pb1 = *(const uint4*)Bg1;

    const int nchunk = E_ >> 5;   // 4
    for (int ch = 0; ch < nchunk; ch++) {
        *(uint4*)((char*)As + swz16(lr,      lu)) = pa0;
        *(uint4*)((char*)As + swz16(lr + 64, lu)) = pa1;
        *(uint4*)((char*)Bs + swz16(lr,      lu)) = pb0;
        *(uint4*)((char*)Bs + swz16(lr + 64, lu)) = pb1;
        __syncthreads();

        if (ch + 1 < nchunk) {
            int ko = (ch + 1) << 5;
            pa0 = *(const uint4*)(Ag0 + ko);
            pa1 = *(const uint4*)(Ag1 + ko);
            pb0 = *(const uint4*)(Bg0 + ko);
            pb1 = *(const uint4*)(Bg1 + ko);
        }

#pragma unroll
        for (int ks = 0; ks < 2; ks++) {
            const int fu = ks * 2 + (lane >> 4);
            const int fr = lane & 15;
            uint32_t af[4][4], bf[4][2];
#pragma unroll
            for (int mt = 0; mt < 4; mt++)
                ldmx4(af[mt], As32 + swz16(wm0 + mt * 16 + fr, fu));
#pragma unroll
            for (int np = 0; np < 2; np++) {
                uint32_t t[4];
                ldmx4(t, Bs32 + swz16(wn0 + np * 16 + fr, fu));
                bf[2 * np][0]     = t[0];
                bf[2 * np + 1][0] = t[1];
                bf[2 * np][1]     = t[2];
                bf[2 * np + 1][1] = t[3];
            }
#pragma unroll
            for (int mt = 0; mt < 4; mt++)
#pragma unroll
                for (int nt = 0; nt < 4; nt++)
                    mma_f16(acc[mt][nt], af[mt], bf[nt]);
        }
        __syncthreads();
    }

    // fast gate epilogue
    const int hi = q & 1;
#pragma unroll
    for (int nt = 0; nt < 4; nt++) {
        const int cn = n0 + wn0 + nt * 8 + 2 * q;
        const float bb0 = g_biasP[cn], bb1 = g_biasP[cn + 1];
        const int u = ((n0 + wn0 + nt * 8) >> 2) + (q >> 1);
#pragma unroll
        for (int mt = 0; mt < 4; mt++) {
            const int m_lo = m0 + wm0 + mt * 16 + g;
            const int m_hi = m_lo + 8;
            float2 rlo = *(const float2*)&g_r[(size_t)(m_lo & 255) * G4 + cn];
            float2 rhi = *(const float2*)&g_r[(size_t)(m_hi & 255) * G4 + cn];
            float p0 = acc[mt][nt][0] + bb0 + rlo.x;
            float p1 = acc[mt][nt][1] + bb1 + rlo.y;
            float p2 = acc[mt][nt][2] + bb0 + rhi.x;
            float p3 = acc[mt][nt][3] + bb1 + rhi.y;
            float r0 = __shfl_xor_sync(0xffffffffu, p0, 1);
            float r1 = __shfl_xor_sync(0xffffffffu, p1, 1);
            float r2 = __shfl_xor_sync(0xffffffffu, p2, 1);
            float r3 = __shfl_xor_sync(0xffffffffu, p3, 1);
            float gi = hi ? r2 : p0;
            float gf = hi ? r3 : p1;
            float gg = hi ? p2 : r0;
            float go = hi ? p3 : r1;
            const int m_sel = hi ? m_hi : m_lo;
            const int b_sel = m_sel & 255;
            float cprev = g_c[(size_t)b_sel * H_ + u];
            float c = fsig(gf) * cprev + fsig(gi) * ftanh(gg);
            float h = fsig(go) * ftanh(c);
            g_HoutH[(size_t)m_sel * H_ + u] = __float2half_rn(h);
        }
    }
}

// ---------------- final: out = sigmoid(Z2 @ W3 + b3), remap (t,b) -> (b,t) ----------------
__global__ void final_dot(const float* __restrict__ W3, const float* __restrict__ b3,
                          float* __restrict__ out)
{
    int row  = blockIdx.x * 8 + (threadIdx.x >> 5);
    int lane = threadIdx.x & 31;
    float4 z = *(const float4*)&g_Z2[row * P2_ + lane * 4];
    float4 w = *(const float4*)&W3[lane * 4];
    float s = z.x * w.x + z.y * w.y + z.z * w.z + z.w * w.w;
#pragma unroll
    for (int o = 16; o > 0; o >>= 1) s += __shfl_xor_sync(0xffffffffu, s, o);
    if (lane == 0) {
        int tt = row >> 8, b = row & 255;
        out[b * T_ + tt] = fsig(s + b3[0]);
    }
}

// ---------------- launcher ----------------
extern "C" void kernel_launch(void* const* d_in, const int* in_sizes, int n_in,
                              void* d_out, int out_size)
{
    const int*   x    = (const int*)  d_in[0];
    const float* emb  = (const float*)d_in[1];
    const float* Wih  = (const float*)d_in[2];
    const float* Whh  = (const float*)d_in[3];
    const float* bih  = (const float*)d_in[4];
    const float* bhh  = (const float*)d_in[5];
    const float* W1   = (const float*)d_in[6];
    const float* b1   = (const float*)d_in[7];
    const float* W2   = (const float*)d_in[8];
    const float* b2   = (const float*)d_in[9];
    const float* W3   = (const float*)d_in[10];
    const float* b3   = (const float*)d_in[11];
    float* out = (float*)d_out;

    void *peh, *pGxh, *pWihPh, *pbias, *pHoutH, *pZ1h, *pZ2, *pW1h, *pW2h;
    cudaGetSymbolAddress(&peh,    g_eh);
    cudaGetSymbolAddress(&pGxh,   g_Gxh);
    cudaGetSymbolAddress(&pWihPh, g_WihPh);
    cudaGetSymbolAddress(&pbias,  g_biasP);
    cudaGetSymbolAddress(&pHoutH, g_HoutH);
    cudaGetSymbolAddress(&pZ1h,   g_Z1h);
    cudaGetSymbolAddress(&pZ2,    g_Z2);
    cudaGetSymbolAddress(&pW1h,   g_W1h);
    cudaGetSymbolAddress(&pW2h,   g_W2h);

    // 1: fused prep (permute + W1/W2 transpose)
    prep_all<<<G4 + P1_ + P2_, 256>>>(Wih, Whh, bih, bhh, W1, W2);

    // 2: embedding mean
    embed_mean<<<B_ * S_, E_>>>(x, emb);

    // 3: x-part for HIST positions (fp16 out, bias folded)
    gemm_f16<0, 1><<<dim3(G4 / 128, (T_ * B_) / 128), 256>>>(
        (const __half*)peh, (const __half*)pWihPh, (const float*)pbias, pGxh,
        T_ * B_, G4, E_);

    // 4 (PROFILED): all 100 LSTM steps + r = hN@W, st.async/mbarrier persistent kernel
    lstm_persist<<<64, 256>>>();

    // 5: fused tgt GEMM + gates -> Hout fp16
    tgt_fused<<<dim3(G4 / 128, (T_ * B_) / 128), 256>>>();

    // 6-7: MLP (fp16 tensor cores)
    gemm_f16<1, 1><<<dim3(P1_ / 128, (T_ * B_) / 128), 256>>>(
        (const __half*)pHoutH, (const __half*)pW1h, b1, pZ1h, T_ * B_, P1_, H_);
    gemm_f16<1, 0><<<dim3(P2_ / 128, (T_ * B_) / 128), 256>>>(
        (const __half*)pZ1h, (const __half*)pW2h, b2, pZ2, T_ * B_, P2_, P1_);

    // 8: head + layout remap to (B, T)
    final_dot<<<(T_ * B_) / 8, 256>>>(W3, b3, out);
}

// round 11
// speedup vs baseline: 2.3362x; 1.0871x over previous
#include <cuda_runtime.h>
#include <cuda_fp16.h>
#include <math.h>
#include <stdint.h>

// Problem dims
#define B_   256
#define S_   200
#define T_   100
#define F_   10
#define E_   128
#define H_   256
#define G4   1024   // 4*H
#define P1_  512
#define P2_  128

// ---------------- scratch (device globals; no runtime alloc allowed) ----------------
__device__ __half g_eh  [S_*B_*E_];           // e fp16, [s][b][k]
__device__ __half g_Gxh [(size_t)T_*B_*G4];   // x-part+bias fp16, HIST ONLY, [s][b][n']
__device__ __half g_WihPh[G4*E_];             // permuted fp16 [n'][k]
__device__ float  g_WhhP[G4*H_];              // permuted fp32 [n'][k]
__device__ float  g_biasP[G4];
__device__ __half g_W1h[P1_*H_];              // [n][k] fp16
__device__ __half g_W2h[P2_*P1_];             // [n][k] fp16
__device__ float  g_c[B_*H_];                 // final cN [b][u]
__device__ float  g_r[B_*G4];                 // hN @ WhhP^T [b][n']
__device__ __half g_HoutH[T_*B_*H_];          // fp16
__device__ __half g_Z1h[(size_t)T_*B_*P1_];   // fp16
__device__ float  g_Z2[T_*B_*P2_];

// fast gate math via MUFU.TANH (1 MUFU per transcendental instead of 2)
__device__ __forceinline__ float ftanh(float x)
{
    float y;
    asm("tanh.approx.f32 %0, %1;" : "=f"(y) : "f"(x));
    return y;
}
__device__ __forceinline__ float fsig(float x)
{
    return fmaf(ftanh(0.5f * x), 0.5f, 0.5f);
}

__device__ __forceinline__ void mma_f16(float* d, const uint32_t* a, const uint32_t* b)
{
    asm volatile(
        "mma.sync.aligned.m16n8k16.row.col.f32.f16.f16.f32 "
        "{%0,%1,%2,%3}, {%4,%5,%6,%7}, {%8,%9}, {%0,%1,%2,%3};\n"
        : "+f"(d[0]), "+f"(d[1]), "+f"(d[2]), "+f"(d[3])
        : "r"(a[0]), "r"(a[1]), "r"(a[2]), "r"(a[3]), "r"(b[0]), "r"(b[1]));
}

__device__ __forceinline__ void ldmx4(uint32_t* r, uint32_t addr)
{
    asm volatile(
        "ldmatrix.sync.aligned.m8n8.x4.shared.b16 {%0,%1,%2,%3}, [%4];\n"
        : "=r"(r[0]), "=r"(r[1]), "=r"(r[2]), "=r"(r[3]) : "r"(addr));
}

__device__ __forceinline__ uint32_t packh2(float lo, float hi)
{
    __half2 h = __floats2half2_rn(lo, hi);
    return *reinterpret_cast<uint32_t*>(&h);
}

// map local smem address into peer CTA's shared window
__device__ __forceinline__ uint32_t mapa_u32(uint32_t laddr, uint32_t rank)
{
    uint32_t r;
    asm volatile("mapa.shared::cluster.u32 %0, %1, %2;" : "=r"(r) : "r"(laddr), "r"(rank));
    return r;
}

// async remote store: 16B to peer smem, signals peer mbarrier with 16B tx
__device__ __forceinline__ void st_async16(uint32_t raddr, uint4 v, uint32_t rmbar)
{
    asm volatile(
        "st.async.shared::cluster.mbarrier::complete_tx::bytes.v4.b32 "
        "[%0], {%1,%2,%3,%4}, [%5];"
        :: "r"(raddr), "r"(v.x), "r"(v.y), "r"(v.z), "r"(v.w), "r"(rmbar) : "memory");
}

__device__ __forceinline__ void mbar_init(uint32_t mbar, uint32_t cnt)
{
    asm volatile("mbarrier.init.shared.b64 [%0], %1;" :: "r"(mbar), "r"(cnt) : "memory");
}
__device__ __forceinline__ void mbar_expect(uint32_t mbar, uint32_t bytes)
{
    asm volatile("mbarrier.arrive.expect_tx.shared.b64 _, [%0], %1;"
                 :: "r"(mbar), "r"(bytes) : "memory");
}
__device__ __forceinline__ void mbar_wait(uint32_t mbar, uint32_t parity)
{
    uint32_t done;
    asm volatile(
        "{\n\t.reg .pred p;\n\t"
        "mbarrier.try_wait.parity.acquire.cta.shared::cta.b64 p, [%1], %2;\n\t"
        "selp.b32 %0, 1, 0, p;\n\t}"
        : "=r"(done) : "r"(mbar), "r"(parity) : "memory");
    if (!done) {
        asm volatile(
            "{\n\t.reg .pred P1;\n\t"
            "WL_%=:\n\t"
            "mbarrier.try_wait.parity.acquire.cta.shared::cta.b64 P1, [%0], %1, 0x989680;\n\t"
            "@P1 bra.uni WD_%=;\n\t"
            "bra.uni WL_%=;\n\t"
            "WD_%=:\n\t}"
            :: "r"(mbar), "r"(parity) : "memory");
    }
}

// swizzled offset for [rows][32 halfs] tiles, 16B units
__device__ __forceinline__ int swz16(int r, int u)
{
    return (r >> 1) * 128 + (((((r & 1) << 2) | u) ^ ((r >> 1) & 7)) << 4);
}

// ---------------- fused prep: permute + W1/W2 transpose (ONE launch) -----
__global__ void prep_all(const float* __restrict__ Wih, const float* __restrict__ Whh,
                         const float* __restrict__ bih, const float* __restrict__ bhh,
                         const float* __restrict__ W1,  const float* __restrict__ W2)
{
    int blk = blockIdx.x;
    int t   = threadIdx.x;
    if (blk < G4) {                               // permute LSTM weights
        int np  = blk;
        int src = (np & 3) * H_ + (np >> 2);
        if (t < E_) g_WihPh[np * E_ + t] = __float2half_rn(Wih[src * E_ + t]);
        g_WhhP[np * H_ + t] = Whh[src * H_ + t];
        if (t == 0) g_biasP[np] = bih[src] + bhh[src];
    } else if (blk < G4 + P1_) {                  // W1 (H,P1) -> [P1][H] fp16
        int n = blk - G4;
        g_W1h[n * H_ + t] = __float2half_rn(W1[t * P1_ + n]);
    } else {                                      // W2 (P1,P2) -> [P2][P1] fp16
        int n = blk - G4 - P1_;
        g_W2h[n * P1_ + t]       = __float2half_rn(W2[t * P2_ + n]);
        g_W2h[n * P1_ + t + 256] = __float2half_rn(W2[(t + 256) * P2_ + n]);
    }
}

__global__ void embed_mean(const int* __restrict__ x, const float* __restrict__ emb)
{
    int row = blockIdx.x;            // b*S_ + s
    int b = row / S_, s = row % S_;
    const int* xi = x + row * F_;
    int k = threadIdx.x;
    float sum = 0.0f;
#pragma unroll
    for (int f = 0; f < F_; f++) sum += emb[(size_t)xi[f] * E_ + k];
    g_eh[((size_t)s * B_ + b) * E_ + k] = __float2half_rn(sum * (1.0f / (float)F_));
}

// ---------------- fp16 tensor-core GEMM: C = act(A @ B^T + bias) ----------------
template<int RELU, int OUTH>
__global__ void __launch_bounds__(256) gemm_f16(const __half* __restrict__ A,
                                                const __half* __restrict__ Bh,
                                                const float* __restrict__ bias,
                                                void* __restrict__ Cv,
                                                int M, int N, int K)
{
    __shared__ __align__(16) __half As[128 * 32];
    __shared__ __align__(16) __half Bs[128 * 32];

    const int tid  = threadIdx.x;
    const int lane = tid & 31;
    const int warp = tid >> 5;
    const int g    = lane >> 2;
    const int q    = lane & 3;
    const int wm0  = (warp >> 2) << 6;
    const int wn0  = (warp & 3) << 5;
    const int m0   = blockIdx.y << 7;
    const int n0   = blockIdx.x << 7;

    const uint32_t As32 = (uint32_t)__cvta_generic_to_shared(As);
    const uint32_t Bs32 = (uint32_t)__cvta_generic_to_shared(Bs);

    const int lr = tid >> 2;
    const int lu = tid & 3;

    const __half* Ag0 = A  + (size_t)(m0 + lr) * K + lu * 8;
    const __half* Ag1 = Ag0 + (size_t)64 * K;
    const __half* Bg0 = Bh + (size_t)(n0 + lr) * K + lu * 8;
    const __half* Bg1 = Bg0 + (size_t)64 * K;

    float acc[4][4][4];
#pragma unroll
    for (int mi = 0; mi < 4; mi++)
#pragma unroll
        for (int ni = 0; ni < 4; ni++)
#pragma unroll
            for (int r = 0; r < 4; r++) acc[mi][ni][r] = 0.0f;

    uint4 pa0 = *(const uint4*)Ag0;
    uint4 pa1 = *(const uint4*)Ag1;
    uint4 pb0 = *(const uint4*)Bg0;
    uint4 pb1 = *(const uint4*)Bg1;

    const int nchunk = K >> 5;
    for (int ch = 0; ch < nchunk; ch++) {
        *(uint4*)((char*)As + swz16(lr,      lu)) = pa0;
        *(uint4*)((char*)As + swz16(lr + 64, lu)) = pa1;
        *(uint4*)((char*)Bs + swz16(lr,      lu)) = pb0;
        *(uint4*)((char*)Bs + swz16(lr + 64, lu)) = pb1;
        __syncthreads();

        if (ch + 1 < nchunk) {
            int ko = (ch + 1) << 5;
            pa0 = *(const uint4*)(Ag0 + ko);
            pa1 = *(const uint4*)(Ag1 + ko);
            pb0 = *(const uint4*)(Bg0 + ko);
            pb1 = *(const uint4*)(Bg1 + ko);
        }

#pragma unroll
        for (int ks = 0; ks < 2; ks++) {
            const int fu = ks * 2 + (lane >> 4);
            const int fr = lane & 15;
            uint32_t af[4][4], bf[4][2];
#pragma unroll
            for (int mt = 0; mt < 4; mt++)
                ldmx4(af[mt], As32 + swz16(wm0 + mt * 16 + fr, fu));
#pragma unroll
            for (int np = 0; np < 2; np++) {
                uint32_t t[4];
                ldmx4(t, Bs32 + swz16(wn0 + np * 16 + fr, fu));
                bf[2 * np][0]     = t[0];
                bf[2 * np + 1][0] = t[1];
                bf[2 * np][1]     = t[2];
                bf[2 * np + 1][1] = t[3];
            }
#pragma unroll
            for (int mt = 0; mt < 4; mt++)
#pragma unroll
                for (int nt = 0; nt < 4; nt++)
                    mma_f16(acc[mt][nt], af[mt], bf[nt]);
        }
        __syncthreads();
    }

#pragma unroll
    for (int nt = 0; nt < 4; nt++) {
        int cn = n0 + wn0 + nt * 8 + 2 * q;
        float bb0 = bias[cn], bb1 = bias[cn + 1];
#pragma unroll
        for (int mt = 0; mt < 4; mt++) {
            int r0 = m0 + wm0 + mt * 16 + g;
            float v0 = acc[mt][nt][0] + bb0;
            float v1 = acc[mt][nt][1] + bb1;
            float v2 = acc[mt][nt][2] + bb0;
            float v3 = acc[mt][nt][3] + bb1;
            if (RELU) {
                v0 = fmaxf(v0, 0.f); v1 = fmaxf(v1, 0.f);
                v2 = fmaxf(v2, 0.f); v3 = fmaxf(v3, 0.f);
            }
            if (OUTH) {
                __half* Ch = (__half*)Cv;
                *(__half2*)&Ch[(size_t)r0 * N + cn]       = __floats2half2_rn(v0, v1);
                *(__half2*)&Ch[(size_t)(r0 + 8) * N + cn] = __floats2half2_rn(v2, v3);
            } else {
                float* Cf = (float*)Cv;
                *(float2*)&Cf[(size_t)r0 * N + cn]       = make_float2(v0, v1);
                *(float2*)&Cf[(size_t)(r0 + 8) * N + cn] = make_float2(v2, v3);
            }
        }
    }
}

// ---------------- persistent fp16 LSTM: 8 clusters x 8 CTAs, st.async + mbarrier -----
// Cluster = batch group of 32 rows; CTA = n' slice [rank*128,+128) -> units [rank*32,+32).
// h-exchange via st.async into peers' double-buffered swizzled tile + inbox mbarrier.
// R11: MUFU.TANH gate math (half the MUFU traffic) and Gx prefetched one step ahead
// (loads issued after the sends, landing during the next wait+mma).
__global__ void __launch_bounds__(256, 1) __cluster_dims__(8, 1, 1) lstm_persist()
{
    __shared__ __align__(16) unsigned char Asm[2][32 * 512]; // h tile double buffer (32KB)
    __shared__ __align__(16) __half hstg[32 * 32];           // h slice staging (2KB)
    __shared__ __align__(8)  uint64_t mbar_s[2];             // inbox mbarriers (per buffer)

    const int tid  = threadIdx.x;
    const int lane = tid & 31;
    const int warp = tid >> 5;
    const int g    = lane >> 2;
    const int q    = lane & 3;
    const int wn   = warp;                 // 8 warps x 16 n'
    const int grp  = blockIdx.x >> 3;      // batch group 0..7 (32 rows each)
    const int rank = blockIdx.x & 7;       // cluster rank = n' slice
    const int b0   = grp << 5;
    const int np0  = rank << 7;            // 128 n' per CTA
    const int u0   = rank << 5;            // 32 units per CTA

    const uint32_t asm_u32  = (uint32_t)__cvta_generic_to_shared(&Asm[0][0]);
    const uint32_t mbar_u32 = (uint32_t)__cvta_generic_to_shared(&mbar_s[0]);

    // zero buffer 0 (h0 = 0); peers' step-0 writes go to buffer 1 (disjoint)
#pragma unroll
    for (int it = 0; it < 4; it++)
        ((uint4*)&Asm[0][0])[tid + it * 256] = make_uint4(0, 0, 0, 0);

    // init inbox mbarriers (count=1: the local expect_tx arrival per phase)
    if (tid == 0) {
        mbar_init(mbar_u32,     1);
        mbar_init(mbar_u32 + 8, 1);
    }
    __syncthreads();

    // W fragments into registers (once): warp covers 16 n' (nt=2)
    uint32_t br[2][16][2];
#pragma unroll
    for (int nt = 0; nt < 2; nt++) {
        const int np = np0 + wn * 16 + nt * 8 + g;
        const float* wp = g_WhhP + (size_t)np * H_;
#pragma unroll
        for (int kc = 0; kc < 16; kc++) {
            float2 lo = *(const float2*)&wp[kc * 16 + 2 * q];
            float2 hi = *(const float2*)&wp[kc * 16 + 2 * q + 8];
            br[nt][kc][0] = packh2(lo.x, lo.y);
            br[nt][kc][1] = packh2(hi.x, hi.y);
        }
    }

    // ldmatrix addresses: 2 m-tiles cover the 32 batch rows
    uint32_t abase[2]; int axor[2];
#pragma unroll
    for (int mt = 0; mt < 2; mt++) {
        int ar = mt * 16 + (lane & 15);
        abase[mt] = asm_u32 + ar * 512;
        axor[mt]  = (ar & 7) << 4;
    }
    const int acol0 = (lane >> 4) * 16;

    // Gx addresses for this thread (fixed across steps up to the s-stride)
    const int gx_bg[2] = { b0 + 0 * 16 + g, b0 + 1 * 16 + g };
    const int gx_nc    = np0 + wn * 16 + 2 * q;   // nt=0 base; nt=1 at +8

    // DSMEM write target (this thread's 16B unit of the CTA's h-slice), rank-invariant
    const int wrow = tid >> 2, wj = tid & 3;
    const int wcu  = rank * 4 + wj;        // 16B-unit column in the full 256-unit tile
    const uint32_t woff = wrow * 512 + ((wcu * 16) ^ ((wrow & 7) << 4));

    // cluster hygiene: all peers' mbarriers and buffers initialized before any st.async
    asm volatile("barrier.cluster.arrive.aligned;" ::: "memory");
    asm volatile("barrier.cluster.wait.aligned;" ::: "memory");

    float cst[2][2] = {{0.f, 0.f}, {0.f, 0.f}};
    uint32_t ph[2] = {0, 0};               // parity tracker per inbox mbar

    // ---- preload Gx for s = 0 ----
    __half2 gxv[2][2][2];
#pragma unroll
    for (int mt = 0; mt < 2; mt++)
#pragma unroll
        for (int nt = 0; nt < 2; nt++) {
            const __half* gp = g_Gxh + ((size_t)0 * B_ + gx_bg[mt]) * G4 + gx_nc + nt * 8;
            gxv[mt][nt][0] = *(const __half2*)gp;
            gxv[mt][nt][1] = *(const __half2*)(gp + (size_t)8 * G4);
        }

    for (int s = 0; s <= T_; s++) {
        const uint32_t bufoff = (uint32_t)(s & 1) * 16384;

        // wait for this step's inbox (s=0 reads the locally-zeroed buffer)
        if (s > 0) {
            mbar_wait(mbar_u32 + (uint32_t)(s & 1) * 8, ph[s & 1]);
            ph[s & 1] ^= 1;
        }

        // mma mainloop straight out of local smem
        float acc[2][2][4];
#pragma unroll
        for (int mt = 0; mt < 2; mt++)
#pragma unroll
            for (int nt = 0; nt < 2; nt++)
#pragma unroll
                for (int r = 0; r < 4; r++) acc[mt][nt][r] = 0.f;

#pragma unroll
        for (int kc = 0; kc < 16; kc++) {
            uint32_t af[2][4];
#pragma unroll
            for (int mt = 0; mt < 2; mt++)
                ldmx4(af[mt], abase[mt] + bufoff + ((acol0 + kc * 32) ^ axor[mt]));
#pragma unroll
            for (int mt = 0; mt < 2; mt++) {
                mma_f16(acc[mt][0], af[mt], br[0][kc]);
                mma_f16(acc[mt][1], af[mt], br[1][kc]);
            }
        }

        if (s < T_) {
            // gate epilogue (MUFU.TANH) -> smem staging
            const int hi = q & 1;
#pragma unroll
            for (int mt = 0; mt < 2; mt++)
#pragma unroll
                for (int nt = 0; nt < 2; nt++) {
                    float2 glo = __half22float2(gxv[mt][nt][0]);
                    float2 ghi = __half22float2(gxv[mt][nt][1]);
                    float p0 = acc[mt][nt][0] + glo.x;
                    float p1 = acc[mt][nt][1] + glo.y;
                    float p2 = acc[mt][nt][2] + ghi.x;
                    float p3 = acc[mt][nt][3] + ghi.y;
                    float r0 = __shfl_xor_sync(0xffffffffu, p0, 1);
                    float r1 = __shfl_xor_sync(0xffffffffu, p1, 1);
                    float r2 = __shfl_xor_sync(0xffffffffu, p2, 1);
                    float r3 = __shfl_xor_sync(0xffffffffu, p3, 1);
                    float gi = hi ? r2 : p0;
                    float gf = hi ? r3 : p1;
                    float gg = hi ? p2 : r0;
                    float go = hi ? p3 : r1;
                    float c  = fsig(gf) * cst[mt][nt] + fsig(gi) * ftanh(gg);
                    cst[mt][nt] = c;
                    float h  = fsig(go) * ftanh(c);
                    const int bl = mt * 16 + g + (hi ? 8 : 0);
                    const int ul = wn * 4 + nt * 2 + (q >> 1);
                    hstg[bl * 32 + ul] = __float2half_rn(h);
                }
            __syncthreads();

            // register local expect for next step's inbox, then broadcast slice
            const uint32_t nb = (uint32_t)((s + 1) & 1);
            if (tid == 0) mbar_expect(mbar_u32 + nb * 8, 16384u);
            if (tid < 128) {
                uint4 v = *(uint4*)&hstg[wrow * 32 + wj * 8];
                const uint32_t dsto = asm_u32 + (bufoff ^ 16384u) + woff;
                const uint32_t mbo  = mbar_u32 + nb * 8;
#pragma unroll
                for (uint32_t pr = 0; pr < 8; pr++)
                    st_async16(mapa_u32(dsto, pr), v, mapa_u32(mbo, pr));
            }

            // prefetch Gx for step s+1 (lands during next wait + mma)
            if (s + 1 < T_) {
#pragma unroll
                for (int mt = 0; mt < 2; mt++)
#pragma unroll
                    for (int nt = 0; nt < 2; nt++) {
                        const __half* gp = g_Gxh +
                            ((size_t)(s + 1) * B_ + gx_bg[mt]) * G4 + gx_nc + nt * 8;
                        gxv[mt][nt][0] = *(const __half2*)gp;
                        gxv[mt][nt][1] = *(const __half2*)(gp + (size_t)8 * G4);
                    }
            }
        } else {
            // s == T_: export r = hN @ W^T and cN
            const int hi = q & 1;
#pragma unroll
            for (int mt = 0; mt < 2; mt++)
#pragma unroll
                for (int nt = 0; nt < 2; nt++) {
                    const int m_lo = b0 + mt * 16 + g;
                    const int nc = np0 + wn * 16 + nt * 8 + 2 * q;
                    *(float2*)&g_r[(size_t)m_lo * G4 + nc] =
                        make_float2(acc[mt][nt][0], acc[mt][nt][1]);
                    *(float2*)&g_r[(size_t)(m_lo + 8) * G4 + nc] =
                        make_float2(acc[mt][nt][2], acc[mt][nt][3]);
                    const int b = m_lo + (hi ? 8 : 0);
                    const int u = u0 + wn * 4 + nt * 2 + (q >> 1);
                    g_c[(size_t)b * H_ + u] = cst[mt][nt];
                }
        }
    }

    // final cluster barrier: no CTA exits while peers' async stores could be in flight
    asm volatile("barrier.cluster.arrive.aligned;" ::: "memory");
    asm volatile("barrier.cluster.wait.aligned;" ::: "memory");
}

// ---------------- fused tgt kernel: gates(e_tgt @ WihP^T + bias + r[b]) -> Hout fp16 ----
__global__ void __launch_bounds__(256) tgt_fused()
{
    __shared__ __align__(16) __half As[128 * 32];
    __shared__ __align__(16) __half Bs[128 * 32];

    const int tid  = threadIdx.x;
    const int lane = tid & 31;
    const int warp = tid >> 5;
    const int g    = lane >> 2;
    const int q    = lane & 3;
    const int wm0  = (warp >> 2) << 6;
    const int wn0  = (warp & 3) << 5;
    const int m0   = blockIdx.y << 7;
    const int n0   = blockIdx.x << 7;

    const uint32_t As32 = (uint32_t)__cvta_generic_to_shared(As);
    const uint32_t Bs32 = (uint32_t)__cvta_generic_to_shared(Bs);

    const int lr = tid >> 2;
    const int lu = tid & 3;

    const __half* A = g_eh + (size_t)T_ * B_ * E_;   // tgt rows
    const __half* Ag0 = A + (size_t)(m0 + lr) * E_ + lu * 8;
    const __half* Ag1 = Ag0 + (size_t)64 * E_;
    const __half* Bg0 = g_WihPh + (size_t)(n0 + lr) * E_ + lu * 8;
    const __half* Bg1 = Bg0 + (size_t)64 * E_;

    float acc[4][4][4];
#pragma unroll
    for (int mi = 0; mi < 4; mi++)
#pragma unroll
        for (int ni = 0; ni < 4; ni++)
#pragma unroll
            for (int r = 0; r < 4; r++) acc[mi][ni][r] = 0.0f;

    uint4 pa0 = *(const uint4*)Ag0;
    uint4 pa1 = *(const uint4*)Ag1;
    uint4 pb0 = *(const uint4*)Bg0;
    uint4 pb1 = *(const uint4*)Bg1;

    const int nchunk = E_ >> 5;   // 4
    for (int ch = 0; ch < nchunk; ch++) {
        *(uint4*)((char*)As + swz16(lr,      lu)) = pa0;
        *(uint4*)((char*)As + swz16(lr + 64, lu)) = pa1;
        *(uint4*)((char*)Bs + swz16(lr,      lu)) = pb0;
        *(uint4*)((char*)Bs + swz16(lr + 64, lu)) = pb1;
        __syncthreads();

        if (ch + 1 < nchunk) {
            int ko = (ch + 1) << 5;
            pa0 = *(const uint4*)(Ag0 + ko);
            pa1 = *(const uint4*)(Ag1 + ko);
            pb0 = *(const uint4*)(Bg0 + ko);
            pb1 = *(const uint4*)(Bg1 + ko);
        }

#pragma unroll
        for (int ks = 0; ks < 2; ks++) {
            const int fu = ks * 2 + (lane >> 4);
            const int fr = lane & 15;
            uint32_t af[4][4], bf[4][2];
#pragma unroll
            for (int mt = 0; mt < 4; mt++)
                ldmx4(af[mt], As32 + swz16(wm0 + mt * 16 + fr, fu));
#pragma unroll
            for (int np = 0; np < 2; np++) {
                uint32_t t[4];
                ldmx4(t, Bs32 + swz16(wn0 + np * 16 + fr, fu));
                bf[2 * np][0]     = t[0];
                bf[2 * np + 1][0] = t[1];
                bf[2 * np][1]     = t[2];
                bf[2 * np + 1][1] = t[3];
            }
#pragma unroll
            for (int mt = 0; mt < 4; mt++)
#pragma unroll
                for (int nt = 0; nt < 4; nt++)
                    mma_f16(acc[mt][nt], af[mt], bf[nt]);
        }
        __syncthreads();
    }

    // fast gate epilogue (MUFU.TANH)
    const int hi = q & 1;
#pragma unroll
    for (int nt = 0; nt < 4; nt++) {
        const int cn = n0 + wn0 + nt * 8 + 2 * q;
        const float bb0 = g_biasP[cn], bb1 = g_biasP[cn + 1];
        const int u = ((n0 + wn0 + nt * 8) >> 2) + (q >> 1);
#pragma unroll
        for (int mt = 0; mt < 4; mt++) {
            const int m_lo = m0 + wm0 + mt * 16 + g;
            const int m_hi = m_lo + 8;
            float2 rlo = *(const float2*)&g_r[(size_t)(m_lo & 255) * G4 + cn];
            float2 rhi = *(const float2*)&g_r[(size_t)(m_hi & 255) * G4 + cn];
            float p0 = acc[mt][nt][0] + bb0 + rlo.x;
            float p1 = acc[mt][nt][1] + bb1 + rlo.y;
            float p2 = acc[mt][nt][2] + bb0 + rhi.x;
            float p3 = acc[mt][nt][3] + bb1 + rhi.y;
            float r0 = __shfl_xor_sync(0xffffffffu, p0, 1);
            float r1 = __shfl_xor_sync(0xffffffffu, p1, 1);
            float r2 = __shfl_xor_sync(0xffffffffu, p2, 1);
            float r3 = __shfl_xor_sync(0xffffffffu, p3, 1);
            float gi = hi ? r2 : p0;
            float gf = hi ? r3 : p1;
            float gg = hi ? p2 : r0;
            float go = hi ? p3 : r1;
            const int m_sel = hi ? m_hi : m_lo;
            const int b_sel = m_sel & 255;
            float cprev = g_c[(size_t)b_sel * H_ + u];
            float c = fsig(gf) * cprev + fsig(gi) * ftanh(gg);
            float h = fsig(go) * ftanh(c);
            g_HoutH[(size_t)m_sel * H_ + u] = __float2half_rn(h);
        }
    }
}

// ---------------- final: out = sigmoid(Z2 @ W3 + b3), remap (t,b) -> (b,t) ----------------
__global__ void final_dot(const float* __restrict__ W3, const float* __restrict__ b3,
                          float* __restrict__ out)
{
    int row  = blockIdx.x * 8 + (threadIdx.x >> 5);
    int lane = threadIdx.x & 31;
    float4 z = *(const float4*)&g_Z2[row * P2_ + lane * 4];
    float4 w = *(const float4*)&W3[lane * 4];
    float s = z.x * w.x + z.y * w.y + z.z * w.z + z.w * w.w;
#pragma unroll
    for (int o = 16; o > 0; o >>= 1) s += __shfl_xor_sync(0xffffffffu, s, o);
    if (lane == 0) {
        int tt = row >> 8, b = row & 255;
        out[b * T_ + tt] = fsig(s + b3[0]);
    }
}

// ---------------- launcher ----------------
extern "C" void kernel_launch(void* const* d_in, const int* in_sizes, int n_in,
                              void* d_out, int out_size)
{
    const int*   x    = (const int*)  d_in[0];
    const float* emb  = (const float*)d_in[1];
    const float* Wih  = (const float*)d_in[2];
    const float* Whh  = (const float*)d_in[3];
    const float* bih  = (const float*)d_in[4];
    const float* bhh  = (const float*)d_in[5];
    const float* W1   = (const float*)d_in[6];
    const float* b1   = (const float*)d_in[7];
    const float* W2   = (const float*)d_in[8];
    const float* b2   = (const float*)d_in[9];
    const float* W3   = (const float*)d_in[10];
    const float* b3   = (const float*)d_in[11];
    float* out = (float*)d_out;

    void *peh, *pGxh, *pWihPh, *pbias, *pHoutH, *pZ1h, *pZ2, *pW1h, *pW2h;
    cudaGetSymbolAddress(&peh,    g_eh);
    cudaGetSymbolAddress(&pGxh,   g_Gxh);
    cudaGetSymbolAddress(&pWihPh, g_WihPh);
    cudaGetSymbolAddress(&pbias,  g_biasP);
    cudaGetSymbolAddress(&pHoutH, g_HoutH);
    cudaGetSymbolAddress(&pZ1h,   g_Z1h);
    cudaGetSymbolAddress(&pZ2,    g_Z2);
    cudaGetSymbolAddress(&pW1h,   g_W1h);
    cudaGetSymbolAddress(&pW2h,   g_W2h);

    // 1: fused prep (permute + W1/W2 transpose)
    prep_all<<<G4 + P1_ + P2_, 256>>>(Wih, Whh, bih, bhh, W1, W2);

    // 2: embedding mean
    embed_mean<<<B_ * S_, E_>>>(x, emb);

    // 3: x-part for HIST positions (fp16 out, bias folded)
    gemm_f16<0, 1><<<dim3(G4 / 128, (T_ * B_) / 128), 256>>>(
        (const __half*)peh, (const __half*)pWihPh, (const float*)pbias, pGxh,
        T_ * B_, G4, E_);

    // 4 (PROFILED): all 100 LSTM steps + r = hN@W, st.async/mbarrier persistent kernel
    lstm_persist<<<64, 256>>>();

    // 5: fused tgt GEMM + gates -> Hout fp16
    tgt_fused<<<dim3(G4 / 128, (T_ * B_) / 128), 256>>>();

    // 6-7: MLP (fp16 tensor cores)
    gemm_f16<1, 1><<<dim3(P1_ / 128, (T_ * B_) / 128), 256>>>(
        (const __half*)pHoutH, (const __half*)pW1h, b1, pZ1h, T_ * B_, P1_, H_);
    gemm_f16<1, 0><<<dim3(P2_ / 128, (T_ * B_) / 128), 256>>>(
        (const __half*)pZ1h, (const __half*)pW2h, b2, pZ2, T_ * B_, P2_, P1_);

    // 8: head + layout remap to (B, T)
    final_dot<<<(T_ * B_) / 8, 256>>>(W3, b3, out);
}